// round 11
// baseline (speedup 1.0000x reference)
#include <cuda_runtime.h>
#include <math.h>

// ---- NSA hyperparameters (fixed) ----
#define S_LEN 2048
#define HQ 16
#define HK 2
#define GQA 8
#define D 128
#define KS 32
#define ST 16
#define SEL 64
#define TOPN 16
#define WIN 512
#define TBLK 127
#define NSEL 32
#define TQ 8                        // queries per block (q-tile)
#define SCALE 0.08838834764831845f  // 1/sqrt(128)
#define FULLMASK 0xffffffffu
#define KP 132                      // smem K/V row pitch (floats)

// ---- static device scratch ----
__device__ float    g_cmp_k[HK][TBLK][D];
__device__ float    g_cmp_v[HK][TBLK][D];
__device__ float    g_cmp_o[S_LEN][HQ][D];
__device__ unsigned g_sel_mask[HK][S_LEN];

__device__ __forceinline__ float warp_sum(float v) {
#pragma unroll
    for (int o = 16; o; o >>= 1) v += __shfl_xor_sync(FULLMASK, v, o);
    return v;
}
__device__ __forceinline__ float warp_max(float v) {
#pragma unroll
    for (int o = 16; o; o >>= 1) v = fmaxf(v, __shfl_xor_sync(FULLMASK, v, o));
    return v;
}
__device__ __forceinline__ float2 ffma2(float2 a, float2 b, float2 c) {
    unsigned long long au = *reinterpret_cast<unsigned long long*>(&a);
    unsigned long long bu = *reinterpret_cast<unsigned long long*>(&b);
    unsigned long long cu = *reinterpret_cast<unsigned long long*>(&c);
    unsigned long long du;
    asm("fma.rn.f32x2 %0, %1, %2, %3;" : "=l"(du) : "l"(au), "l"(bu), "l"(cu));
    return *reinterpret_cast<float2*>(&du);
}
__device__ __forceinline__ void cp_async16(float* smem_dst, const float* gmem_src) {
    unsigned sa = (unsigned)__cvta_generic_to_shared(smem_dst);
    asm volatile("cp.async.cg.shared.global [%0], [%1], 16;\n" :: "r"(sa), "l"(gmem_src));
}
#define CP_COMMIT()  asm volatile("cp.async.commit_group;\n" ::: "memory")
#define CP_WAIT(N)   asm volatile("cp.async.wait_group %0;\n" :: "n"(N) : "memory")

// ============================================================
// Kernel 1: compressed K/V blocks
// ============================================================
__global__ void k_compress(const float* __restrict__ k,
                           const float* __restrict__ v,
                           const float* __restrict__ wck,
                           const float* __restrict__ wcv) {
    int t = blockIdx.x;
    int n = blockIdx.y;
    int d = threadIdx.x;
    float ak = 0.f, av = 0.f;
#pragma unroll
    for (int w = 0; w < KS; ++w) {
        int j = t * ST + w;
        size_t idx = ((size_t)j * HK + n) * D + d;
        ak += k[idx] * wck[w];
        av += v[idx] * wcv[w];
    }
    g_cmp_k[n][t][d] = ak;
    g_cmp_v[n][t][d] = av;
}

// ============================================================
// Kernel 2: compressed attention + selection, q-tiled.
// C phase restructured: p read as float4 row-quads (16B aligned).
// ============================================================
__global__ void __launch_bounds__(256) k_cmp_sel(const float* __restrict__ q) {
    extern __shared__ float sm[];
    float* qsm = sm;                    // 8192
    float* kv  = sm + 8192;             // 4224
    float* scb = sm + 8192 + 4224;      // 8192

    int s0 = blockIdx.x * TQ;
    int n = blockIdx.y;
    int tid = threadIdx.x;
    int h = tid >> 5;
    int lane = tid & 31;

    for (int u = tid; u < 2048; u += 256) {
        int qi = u >> 8, rem = u & 255, hh = rem >> 5, d4 = rem & 31;
        *reinterpret_cast<float4*>(qsm + (qi * 8 + hh) * 128 + 4 * d4) =
            *reinterpret_cast<const float4*>(
                q + ((size_t)(s0 + qi) * HQ + n * GQA + hh) * D + 4 * d4);
    }
    int s_max = s0 + TQ - 1;
    int Tvm = (s_max >= KS - 1) ? (s_max - (KS - 1)) / ST + 1 : 0;
    int ct = (Tvm + 31) >> 5;
    __syncthreads();

    // ---- A: raw scores ----
    for (int c = 0; c < ct; ++c) {
        for (int u = tid; u < 1024; u += 256) {
            int row = u >> 5, d4 = u & 31;
            int t = c * 32 + row; if (t > TBLK - 1) t = TBLK - 1;
            *reinterpret_cast<float4*>(kv + row * KP + 4 * d4) =
                *reinterpret_cast<const float4*>(&g_cmp_k[n][t][4 * d4]);
        }
        __syncthreads();
        float2 a2[TQ];
#pragma unroll
        for (int r = 0; r < TQ; ++r) a2[r] = make_float2(0.f, 0.f);
#pragma unroll 8
        for (int d4 = 0; d4 < 32; ++d4) {
            float4 kk = *reinterpret_cast<const float4*>(kv + lane * KP + 4 * d4);
#pragma unroll
            for (int r = 0; r < TQ; ++r) {
                float4 qq = *reinterpret_cast<const float4*>(qsm + (r * 8 + h) * 128 + 4 * d4);
                a2[r] = ffma2({qq.x, qq.y}, {kk.x, kk.y}, a2[r]);
                a2[r] = ffma2({qq.z, qq.w}, {kk.z, kk.w}, a2[r]);
            }
        }
#pragma unroll
        for (int r = 0; r < TQ; ++r)
            scb[(h * 8 + r) * 128 + c * 32 + lane] = (a2[r].x + a2[r].y) * SCALE;
        __syncthreads();
    }

    // ---- B: per-row softmax ----
#pragma unroll
    for (int r = 0; r < TQ; ++r) {
        int s_r = s0 + r;
        int Tv = (s_r >= KS - 1) ? (s_r - (KS - 1)) / ST + 1 : 0;
        float* row = scb + (h * 8 + r) * 128;
        if (Tv == 0) {
            reinterpret_cast<float4*>(row)[lane] = make_float4(0.f, 0.f, 0.f, 0.f);
            continue;
        }
        float4 v4 = reinterpret_cast<float4*>(row)[lane];
        int tb = 4 * lane;
        float m = fmaxf(fmaxf(tb + 0 < Tv ? v4.x : -INFINITY, tb + 1 < Tv ? v4.y : -INFINITY),
                        fmaxf(tb + 2 < Tv ? v4.z : -INFINITY, tb + 3 < Tv ? v4.w : -INFINITY));
        m = warp_max(m);
        float e0 = tb + 0 < Tv ? __expf(v4.x - m) : 0.f;
        float e1 = tb + 1 < Tv ? __expf(v4.y - m) : 0.f;
        float e2 = tb + 2 < Tv ? __expf(v4.z - m) : 0.f;
        float e3 = tb + 3 < Tv ? __expf(v4.w - m) : 0.f;
        float l = warp_sum(e0 + e1 + e2 + e3);
        float inv = 1.f / l;
        reinterpret_cast<float4*>(row)[lane] =
            make_float4(e0 * inv, e1 * inv, e2 * inv, e3 * inv);
    }
    __syncthreads();

    // ---- C: PV -> g_cmp_o (token-quad restructure) ----
    float2 aC[TQ][2];
#pragma unroll
    for (int r = 0; r < TQ; ++r) { aC[r][0] = {0.f, 0.f}; aC[r][1] = {0.f, 0.f}; }
    for (int c = 0; c < ct; ++c) {
        for (int u = tid; u < 1024; u += 256) {
            int row = u >> 5, d4 = u & 31;
            int t = c * 32 + row; if (t > TBLK - 1) t = TBLK - 1;
            *reinterpret_cast<float4*>(kv + row * KP + 4 * d4) =
                *reinterpret_cast<const float4*>(&g_cmp_v[n][t][4 * d4]);
        }
        __syncthreads();
#pragma unroll
        for (int tq = 0; tq < 8; ++tq) {
            float4 vv0 = *reinterpret_cast<const float4*>(kv + (4 * tq + 0) * KP + 4 * lane);
            float4 vv1 = *reinterpret_cast<const float4*>(kv + (4 * tq + 1) * KP + 4 * lane);
            float4 vv2 = *reinterpret_cast<const float4*>(kv + (4 * tq + 2) * KP + 4 * lane);
            float4 vv3 = *reinterpret_cast<const float4*>(kv + (4 * tq + 3) * KP + 4 * lane);
#pragma unroll
            for (int r = 0; r < TQ; ++r) {
                float4 pq = *reinterpret_cast<const float4*>(
                    scb + (h * 8 + r) * 128 + c * 32 + 4 * tq);
                aC[r][0] = ffma2({pq.x, pq.x}, {vv0.x, vv0.y}, aC[r][0]);
                aC[r][1] = ffma2({pq.x, pq.x}, {vv0.z, vv0.w}, aC[r][1]);
                aC[r][0] = ffma2({pq.y, pq.y}, {vv1.x, vv1.y}, aC[r][0]);
                aC[r][1] = ffma2({pq.y, pq.y}, {vv1.z, vv1.w}, aC[r][1]);
                aC[r][0] = ffma2({pq.z, pq.z}, {vv2.x, vv2.y}, aC[r][0]);
                aC[r][1] = ffma2({pq.z, pq.z}, {vv2.z, vv2.w}, aC[r][1]);
                aC[r][0] = ffma2({pq.w, pq.w}, {vv3.x, vv3.y}, aC[r][0]);
                aC[r][1] = ffma2({pq.w, pq.w}, {vv3.z, vv3.w}, aC[r][1]);
            }
        }
        __syncthreads();
    }
#pragma unroll
    for (int r = 0; r < TQ; ++r) {
        float4 o4 = make_float4(aC[r][0].x, aC[r][0].y, aC[r][1].x, aC[r][1].y);
        *reinterpret_cast<float4*>(&g_cmp_o[s0 + r][n * GQA + h][4 * lane]) = o4;
    }

    // ---- D: p_slc + top-16 (warp = query) ----
    {
        int r = h;
        int s_r = s0 + r;
        int m = lane;
        float pm = 0.f;
        int tlo = 4 * m - 1; if (tlo < 0) tlo = 0;
        int thi = 4 * m + 3; if (thi > 127) thi = 127;
        for (int t = tlo; t <= thi; ++t) {
#pragma unroll
            for (int hh = 0; hh < 8; ++hh) pm += scb[(hh * 8 + r) * 128 + t];
        }
        int cur = s_r >> 6;
        bool forced = (m == 0) || (m == cur);
        bool causal = (m <= cur);
        float val = forced ? 1e30f : (causal ? pm : -1e30f);
        unsigned msk = 0;
        for (int it = 0; it < TOPN; ++it) {
            float bv = val;
            int bi = lane;
#pragma unroll
            for (int o = 16; o; o >>= 1) {
                float ov = __shfl_xor_sync(FULLMASK, bv, o);
                int oi = __shfl_xor_sync(FULLMASK, bi, o);
                if (ov > bv || (ov == bv && oi < bi)) { bv = ov; bi = oi; }
            }
            if (bv > -5e29f) msk |= (1u << bi);
            if (lane == bi) val = -INFINITY;
        }
        if (lane == 0) g_sel_mask[n][s_r] = msk;
    }
}

// ============================================================
// Kernel 3: main attention, q-tiled, cp.async pipelined,
// max-free softmax, PV specialized by tile category.
// psm reads are float2 (8B-aligned; float4 at pitch-18 is UB).
// ============================================================
__global__ void __launch_bounds__(256, 2) k_main_attn(const float* __restrict__ q,
                                                      const float* __restrict__ kg,
                                                      const float* __restrict__ vg,
                                                      const float* __restrict__ wg,
                                                      const float* __restrict__ bg,
                                                      float* __restrict__ out) {
    extern __shared__ float sm[];
    float* qsm  = sm;                         // 8192
    float* ksm0 = sm + 8192;                  // 4224
    float* ksm1 = sm + 8192 + 4224;           // 4224
    float* vsm  = sm + 8192 + 8448;           // 4224
    float* psm  = sm + 8192 + 12672;          // 4608
    int*   tli  = reinterpret_cast<int*>(sm + 8192 + 12672 + 4608);

    int s0 = (int)(gridDim.x - 1 - blockIdx.x) * TQ;  // long blocks first
    int n = blockIdx.y;
    int tid = threadIdx.x;
    int h = tid >> 5;
    int lane = tid & 31;
    int s_max = s0 + TQ - 1;

    int st_row = tid >> 5;
    int st_d4 = tid & 31;

    for (int u = tid; u < 2048; u += 256) {
        int qi = u >> 8, rem = u & 255, hh = rem >> 5, d4 = rem & 31;
        *reinterpret_cast<float4*>(qsm + (qi * 8 + hh) * 128 + 4 * d4) =
            *reinterpret_cast<const float4*>(
                q + ((size_t)(s0 + qi) * HQ + n * GQA + hh) * D + 4 * d4);
    }
    if (tid == 0) {
        unsigned orm = 0;
#pragma unroll
        for (int r = 0; r < TQ; ++r) {
            unsigned mk = g_sel_mask[n][s0 + r];
            tli[r] = (int)mk;
            orm |= mk;
        }
        int winlo0 = s0 - WIN; if (winlo0 < 0) winlo0 = 0;
        int cur_max = s_max >> 6;
        int c = 0;
        for (int b = 0; b <= cur_max; ++b) {
            bool anysel = (orm >> b) & 1u;
            for (int half = 0; half < 2; ++half) {
                int t0 = (b << 6) + half * 32;
                if (t0 > s_max) break;
                if (anysel || (t0 + 31 >= winlo0)) tli[8 + c++] = t0;
            }
        }
        tli[72] = c;
    }
    __syncthreads();
    int nt = tli[72];

    float lS[TQ], lW[TQ];
    float2 aS[TQ][2], aW[TQ][2], aB[TQ][2];
#pragma unroll
    for (int r = 0; r < TQ; ++r) {
        lS[r] = 0.f; lW[r] = 0.f;
        aS[r][0] = {0.f, 0.f}; aS[r][1] = {0.f, 0.f};
        aW[r][0] = {0.f, 0.f}; aW[r][1] = {0.f, 0.f};
        aB[r][0] = {0.f, 0.f}; aB[r][1] = {0.f, 0.f};
    }

    // ---- prologue: prefetch K(0) ----
    if (nt > 0) {
        int t0 = tli[8];
#pragma unroll
        for (int rr = 0; rr < 4; ++rr) {
            int row = st_row + 8 * rr;
            cp_async16(ksm0 + row * KP + 4 * st_d4,
                       kg + ((size_t)(t0 + row) * HK + n) * D + 4 * st_d4);
        }
    }
    CP_COMMIT();   // group: K(0)

    for (int i = 0; i < nt; ++i) {
        int t0 = tli[8 + i];
        float* kcur = (i & 1) ? ksm1 : ksm0;
        float* knxt = (i & 1) ? ksm0 : ksm1;
        bool hasnxt = (i + 1 < nt);

        __syncthreads();   // S1: vsm free (PV(i-1) done), knxt free

        // V(i) -> vsm  (own group)
#pragma unroll
        for (int rr = 0; rr < 4; ++rr) {
            int row = st_row + 8 * rr;
            cp_async16(vsm + row * KP + 4 * st_d4,
                       vg + ((size_t)(t0 + row) * HK + n) * D + 4 * st_d4);
        }
        CP_COMMIT();   // group: V(i)

        if (hasnxt) {
            int t0n = tli[8 + i + 1];
#pragma unroll
            for (int rr = 0; rr < 4; ++rr) {
                int row = st_row + 8 * rr;
                cp_async16(knxt + row * KP + 4 * st_d4,
                           kg + ((size_t)(t0n + row) * HK + n) * D + 4 * st_d4);
            }
            CP_COMMIT();   // group: K(i+1)
        }

        if (hasnxt) { CP_WAIT(2); } else { CP_WAIT(1); }   // K(i) complete
        __syncthreads();   // S2: K(i) visible

        // per-row flags (warp-uniform; identical across warps)
        int b = t0 >> 6;
        int selb = 0, winb = 0, bothb = 0;
#pragma unroll
        for (int r = 0; r < TQ; ++r) {
            int s_r = s0 + r;
            int wl = s_r - WIN; if (wl < 0) wl = 0;
            bool ok = (t0 <= s_r);
            bool ins = ok && (((unsigned)tli[r] >> b) & 1u);
            if (ins) selb |= 1 << r;
            if (ok && (t0 + 31 >= wl)) winb |= 1 << r;
            if (ins && (t0 >= wl)) bothb |= 1 << r;
        }
        int actb = selb | winb;
        int j = t0 + lane;

        // ---- scores ----
        float2 a2[TQ];
#pragma unroll
        for (int r = 0; r < TQ; ++r) a2[r] = make_float2(0.f, 0.f);
#pragma unroll 8
        for (int d4 = 0; d4 < 32; ++d4) {
            float4 kk = *reinterpret_cast<const float4*>(kcur + lane * KP + 4 * d4);
#pragma unroll
            for (int r = 0; r < TQ; ++r) {
                float4 qq = *reinterpret_cast<const float4*>(qsm + (r * 8 + h) * 128 + 4 * d4);
                a2[r] = ffma2({qq.x, qq.y}, {kk.x, kk.y}, a2[r]);
                a2[r] = ffma2({qq.z, qq.w}, {kk.z, kk.w}, a2[r]);
            }
        }

        // ---- max-free softmax; p -> psm (always written, zeros if idle) ----
#pragma unroll
        for (int r = 0; r < TQ; ++r) {
            float pS = 0.f, pW = 0.f;
            if ((actb >> r) & 1) {
                int s_r = s0 + r;
                int wl = s_r - WIN; if (wl < 0) wl = 0;
                bool ins = (selb >> r) & 1;
                float sc = (a2[r].x + a2[r].y) * SCALE;
                bool contrib = (j <= s_r) && (ins || (j >= wl));
                float pe = contrib ? __expf(sc) : 0.f;
                pS = ins ? pe : 0.f;
                pW = (j >= wl) ? pe : 0.f;
                lS[r] += pS;
                lW[r] += pW;
            }
            *reinterpret_cast<float2*>(psm + ((h * 32 + lane) * 9 + r) * 2) =
                make_float2(pS, pW);
        }
        __syncwarp();

        if (hasnxt) { CP_WAIT(1); } else { CP_WAIT(0); }   // V(i) complete
        __syncthreads();   // S3: V(i) visible

        // ---- PV: specialized by tile category (psm via aligned float2) ----
        if (selb == 0) {
#pragma unroll 4
            for (int tt = 0; tt < 32; ++tt) {
                float4 vv = *reinterpret_cast<const float4*>(vsm + tt * KP + 4 * lane);
                float2 va = {vv.x, vv.y}, vb = {vv.z, vv.w};
                const float* pb = psm + (h * 32 + tt) * 18;
#pragma unroll
                for (int rp = 0; rp < 4; ++rp) {
                    float2 p0 = *reinterpret_cast<const float2*>(pb + 4 * rp);
                    float2 p1 = *reinterpret_cast<const float2*>(pb + 4 * rp + 2);
                    int r0 = 2 * rp, r1 = r0 + 1;
                    aW[r0][0] = ffma2({p0.y, p0.y}, va, aW[r0][0]);
                    aW[r0][1] = ffma2({p0.y, p0.y}, vb, aW[r0][1]);
                    aW[r1][0] = ffma2({p1.y, p1.y}, va, aW[r1][0]);
                    aW[r1][1] = ffma2({p1.y, p1.y}, vb, aW[r1][1]);
                }
            }
        } else if (winb == 0) {
#pragma unroll 4
            for (int tt = 0; tt < 32; ++tt) {
                float4 vv = *reinterpret_cast<const float4*>(vsm + tt * KP + 4 * lane);
                float2 va = {vv.x, vv.y}, vb = {vv.z, vv.w};
                const float* pb = psm + (h * 32 + tt) * 18;
#pragma unroll
                for (int rp = 0; rp < 4; ++rp) {
                    float2 p0 = *reinterpret_cast<const float2*>(pb + 4 * rp);
                    float2 p1 = *reinterpret_cast<const float2*>(pb + 4 * rp + 2);
                    int r0 = 2 * rp, r1 = r0 + 1;
                    aS[r0][0] = ffma2({p0.x, p0.x}, va, aS[r0][0]);
                    aS[r0][1] = ffma2({p0.x, p0.x}, vb, aS[r0][1]);
                    aS[r1][0] = ffma2({p1.x, p1.x}, va, aS[r1][0]);
                    aS[r1][1] = ffma2({p1.x, p1.x}, vb, aS[r1][1]);
                }
            }
        } else if (bothb == 0xFF) {
#pragma unroll 4
            for (int tt = 0; tt < 32; ++tt) {
                float4 vv = *reinterpret_cast<const float4*>(vsm + tt * KP + 4 * lane);
                float2 va = {vv.x, vv.y}, vb = {vv.z, vv.w};
                const float* pb = psm + (h * 32 + tt) * 18;
#pragma unroll
                for (int rp = 0; rp < 4; ++rp) {
                    float2 p0 = *reinterpret_cast<const float2*>(pb + 4 * rp);
                    float2 p1 = *reinterpret_cast<const float2*>(pb + 4 * rp + 2);
                    int r0 = 2 * rp, r1 = r0 + 1;
                    aB[r0][0] = ffma2({p0.x, p0.x}, va, aB[r0][0]);
                    aB[r0][1] = ffma2({p0.x, p0.x}, vb, aB[r0][1]);
                    aB[r1][0] = ffma2({p1.x, p1.x}, va, aB[r1][0]);
                    aB[r1][1] = ffma2({p1.x, p1.x}, vb, aB[r1][1]);
                }
            }
        } else {
#pragma unroll 4
            for (int tt = 0; tt < 32; ++tt) {
                float4 vv = *reinterpret_cast<const float4*>(vsm + tt * KP + 4 * lane);
                float2 va = {vv.x, vv.y}, vb = {vv.z, vv.w};
                const float* pb = psm + (h * 32 + tt) * 18;
#pragma unroll
                for (int rp = 0; rp < 4; ++rp) {
                    float2 p0 = *reinterpret_cast<const float2*>(pb + 4 * rp);
                    float2 p1 = *reinterpret_cast<const float2*>(pb + 4 * rp + 2);
                    int r0 = 2 * rp, r1 = r0 + 1;
                    aS[r0][0] = ffma2({p0.x, p0.x}, va, aS[r0][0]);
                    aS[r0][1] = ffma2({p0.x, p0.x}, vb, aS[r0][1]);
                    aW[r0][0] = ffma2({p0.y, p0.y}, va, aW[r0][0]);
                    aW[r0][1] = ffma2({p0.y, p0.y}, vb, aW[r0][1]);
                    aS[r1][0] = ffma2({p1.x, p1.x}, va, aS[r1][0]);
                    aS[r1][1] = ffma2({p1.x, p1.x}, vb, aS[r1][1]);
                    aW[r1][0] = ffma2({p1.y, p1.y}, va, aW[r1][0]);
                    aW[r1][1] = ffma2({p1.y, p1.y}, vb, aW[r1][1]);
                }
            }
        }
    }

    // ---- finalize: fold shared accumulator, gates, combine ----
#pragma unroll
    for (int r = 0; r < TQ; ++r) {
        int s_r = s0 + r;
        float4 q4 = *reinterpret_cast<const float4*>(qsm + (r * 8 + h) * 128 + 4 * lane);
        float gt[3];
#pragma unroll
        for (int c = 0; c < 3; ++c) {
            float gp = q4.x * wg[(4 * lane + 0) * 3 + c]
                     + q4.y * wg[(4 * lane + 1) * 3 + c]
                     + q4.z * wg[(4 * lane + 2) * 3 + c]
                     + q4.w * wg[(4 * lane + 3) * 3 + c];
            gp = warp_sum(gp) + bg[c];
            gt[c] = 1.f / (1.f + __expf(-gp));
        }
        float sx0 = aS[r][0].x + aB[r][0].x, sy0 = aS[r][0].y + aB[r][0].y;
        float sx1 = aS[r][1].x + aB[r][1].x, sy1 = aS[r][1].y + aB[r][1].y;
        float wx0 = aW[r][0].x + aB[r][0].x, wy0 = aW[r][0].y + aB[r][0].y;
        float wx1 = aW[r][1].x + aB[r][1].x, wy1 = aW[r][1].y + aB[r][1].y;
        float iS = 1.f / warp_sum(lS[r]);
        float iW = 1.f / warp_sum(lW[r]);
        float4 c4 = *reinterpret_cast<const float4*>(&g_cmp_o[s_r][n * GQA + h][4 * lane]);
        float4 o4;
        o4.x = c4.x * gt[0] + sx0 * iS * gt[1] + wx0 * iW * gt[2];
        o4.y = c4.y * gt[0] + sy0 * iS * gt[1] + wy0 * iW * gt[2];
        o4.z = c4.z * gt[0] + sx1 * iS * gt[1] + wx1 * iW * gt[2];
        o4.w = c4.w * gt[0] + sy1 * iS * gt[1] + wy1 * iW * gt[2];
        *reinterpret_cast<float4*>(out + ((size_t)s_r * HQ + n * GQA + h) * D + 4 * lane) = o4;
    }
}

// ============================================================
// launch  (inputs: q, k, v, w_cmp_k, w_cmp_v, w_gate, b_gate)
// ============================================================
extern "C" void kernel_launch(void* const* d_in, const int* in_sizes, int n_in,
                              void* d_out, int out_size) {
    const float* q   = (const float*)d_in[0];
    const float* k   = (const float*)d_in[1];
    const float* v   = (const float*)d_in[2];
    const float* wck = (const float*)d_in[3];
    const float* wcv = (const float*)d_in[4];
    const float* wg  = (const float*)d_in[5];
    const float* bg  = (const float*)d_in[6];
    float* out = (float*)d_out;

    const int smem2 = (8192 + 4224 + 8192) * 4;
    const int smem3 = (8192 + 4224 * 3 + 4608) * 4 + 73 * 4;
    cudaFuncSetAttribute(k_cmp_sel, cudaFuncAttributeMaxDynamicSharedMemorySize, smem2);
    cudaFuncSetAttribute(k_main_attn, cudaFuncAttributeMaxDynamicSharedMemorySize, smem3);

    k_compress<<<dim3(TBLK, HK), D>>>(k, v, wck, wcv);
    k_cmp_sel<<<dim3(S_LEN / TQ, HK), 256, smem2>>>(q);
    k_main_attn<<<dim3(S_LEN / TQ, HK), 256, smem3>>>(q, k, v, wg, bg, out);
}

// round 12
// speedup vs baseline: 1.0487x; 1.0487x over previous
#include <cuda_runtime.h>
#include <math.h>

// ---- NSA hyperparameters (fixed) ----
#define S_LEN 2048
#define HQ 16
#define HK 2
#define GQA 8
#define D 128
#define KS 32
#define ST 16
#define SEL 64
#define TOPN 16
#define WIN 512
#define TBLK 127
#define NSEL 32
#define TQ 8                        // queries per block (q-tile)
#define SCALE 0.08838834764831845f  // 1/sqrt(128)
#define FULLMASK 0xffffffffu
#define KP 132                      // smem K/V row pitch (floats)
#define PSP 20                      // psm pitch per (h,token) in floats (16B-aligned)

// ---- static device scratch ----
__device__ float    g_cmp_k[HK][TBLK][D];
__device__ float    g_cmp_v[HK][TBLK][D];
__device__ float    g_cmp_o[S_LEN][HQ][D];
__device__ unsigned g_sel_mask[HK][S_LEN];

__device__ __forceinline__ float warp_sum(float v) {
#pragma unroll
    for (int o = 16; o; o >>= 1) v += __shfl_xor_sync(FULLMASK, v, o);
    return v;
}
__device__ __forceinline__ float warp_max(float v) {
#pragma unroll
    for (int o = 16; o; o >>= 1) v = fmaxf(v, __shfl_xor_sync(FULLMASK, v, o));
    return v;
}
__device__ __forceinline__ float2 ffma2(float2 a, float2 b, float2 c) {
    unsigned long long au = *reinterpret_cast<unsigned long long*>(&a);
    unsigned long long bu = *reinterpret_cast<unsigned long long*>(&b);
    unsigned long long cu = *reinterpret_cast<unsigned long long*>(&c);
    unsigned long long du;
    asm("fma.rn.f32x2 %0, %1, %2, %3;" : "=l"(du) : "l"(au), "l"(bu), "l"(cu));
    return *reinterpret_cast<float2*>(&du);
}
__device__ __forceinline__ void cp_async16(float* smem_dst, const float* gmem_src) {
    unsigned sa = (unsigned)__cvta_generic_to_shared(smem_dst);
    asm volatile("cp.async.cg.shared.global [%0], [%1], 16;\n" :: "r"(sa), "l"(gmem_src));
}
#define CP_COMMIT()  asm volatile("cp.async.commit_group;\n" ::: "memory")
#define CP_WAIT(N)   asm volatile("cp.async.wait_group %0;\n" :: "n"(N) : "memory")

// ============================================================
// Kernel 1: compressed K/V blocks
// ============================================================
__global__ void k_compress(const float* __restrict__ k,
                           const float* __restrict__ v,
                           const float* __restrict__ wck,
                           const float* __restrict__ wcv) {
    int t = blockIdx.x;
    int n = blockIdx.y;
    int d = threadIdx.x;
    float ak = 0.f, av = 0.f;
#pragma unroll
    for (int w = 0; w < KS; ++w) {
        int j = t * ST + w;
        size_t idx = ((size_t)j * HK + n) * D + d;
        ak += k[idx] * wck[w];
        av += v[idx] * wcv[w];
    }
    g_cmp_k[n][t][d] = ak;
    g_cmp_v[n][t][d] = av;
}

// ============================================================
// Kernel 2: compressed attention + selection, q-tiled.
// (R5/R9-proven version)
// ============================================================
__global__ void __launch_bounds__(256) k_cmp_sel(const float* __restrict__ q) {
    extern __shared__ float sm[];
    float* qsm = sm;                    // 8192
    float* kv  = sm + 8192;             // 4224
    float* scb = sm + 8192 + 4224;      // 8192

    int s0 = blockIdx.x * TQ;
    int n = blockIdx.y;
    int tid = threadIdx.x;
    int h = tid >> 5;
    int lane = tid & 31;

    for (int u = tid; u < 2048; u += 256) {
        int qi = u >> 8, rem = u & 255, hh = rem >> 5, d4 = rem & 31;
        *reinterpret_cast<float4*>(qsm + (qi * 8 + hh) * 128 + 4 * d4) =
            *reinterpret_cast<const float4*>(
                q + ((size_t)(s0 + qi) * HQ + n * GQA + hh) * D + 4 * d4);
    }
    int s_max = s0 + TQ - 1;
    int Tvm = (s_max >= KS - 1) ? (s_max - (KS - 1)) / ST + 1 : 0;
    int ct = (Tvm + 31) >> 5;
    __syncthreads();

    // ---- A: raw scores ----
    for (int c = 0; c < ct; ++c) {
        for (int u = tid; u < 1024; u += 256) {
            int row = u >> 5, d4 = u & 31;
            int t = c * 32 + row; if (t > TBLK - 1) t = TBLK - 1;
            *reinterpret_cast<float4*>(kv + row * KP + 4 * d4) =
                *reinterpret_cast<const float4*>(&g_cmp_k[n][t][4 * d4]);
        }
        __syncthreads();
        float2 a2[TQ];
#pragma unroll
        for (int r = 0; r < TQ; ++r) a2[r] = make_float2(0.f, 0.f);
#pragma unroll 8
        for (int d4 = 0; d4 < 32; ++d4) {
            float4 kk = *reinterpret_cast<const float4*>(kv + lane * KP + 4 * d4);
#pragma unroll
            for (int r = 0; r < TQ; ++r) {
                float4 qq = *reinterpret_cast<const float4*>(qsm + (r * 8 + h) * 128 + 4 * d4);
                a2[r] = ffma2({qq.x, qq.y}, {kk.x, kk.y}, a2[r]);
                a2[r] = ffma2({qq.z, qq.w}, {kk.z, kk.w}, a2[r]);
            }
        }
#pragma unroll
        for (int r = 0; r < TQ; ++r)
            scb[(h * 8 + r) * 128 + c * 32 + lane] = (a2[r].x + a2[r].y) * SCALE;
        __syncthreads();
    }

    // ---- B: per-row softmax ----
#pragma unroll
    for (int r = 0; r < TQ; ++r) {
        int s_r = s0 + r;
        int Tv = (s_r >= KS - 1) ? (s_r - (KS - 1)) / ST + 1 : 0;
        float* row = scb + (h * 8 + r) * 128;
        if (Tv == 0) {
            reinterpret_cast<float4*>(row)[lane] = make_float4(0.f, 0.f, 0.f, 0.f);
            continue;
        }
        float4 v4 = reinterpret_cast<float4*>(row)[lane];
        int tb = 4 * lane;
        float m = fmaxf(fmaxf(tb + 0 < Tv ? v4.x : -INFINITY, tb + 1 < Tv ? v4.y : -INFINITY),
                        fmaxf(tb + 2 < Tv ? v4.z : -INFINITY, tb + 3 < Tv ? v4.w : -INFINITY));
        m = warp_max(m);
        float e0 = tb + 0 < Tv ? __expf(v4.x - m) : 0.f;
        float e1 = tb + 1 < Tv ? __expf(v4.y - m) : 0.f;
        float e2 = tb + 2 < Tv ? __expf(v4.z - m) : 0.f;
        float e3 = tb + 3 < Tv ? __expf(v4.w - m) : 0.f;
        float l = warp_sum(e0 + e1 + e2 + e3);
        float inv = 1.f / l;
        reinterpret_cast<float4*>(row)[lane] =
            make_float4(e0 * inv, e1 * inv, e2 * inv, e3 * inv);
    }
    __syncthreads();

    // ---- C: PV -> g_cmp_o ----
    float2 aC[TQ][2];
#pragma unroll
    for (int r = 0; r < TQ; ++r) { aC[r][0] = {0.f, 0.f}; aC[r][1] = {0.f, 0.f}; }
    for (int c = 0; c < ct; ++c) {
        for (int u = tid; u < 1024; u += 256) {
            int row = u >> 5, d4 = u & 31;
            int t = c * 32 + row; if (t > TBLK - 1) t = TBLK - 1;
            *reinterpret_cast<float4*>(kv + row * KP + 4 * d4) =
                *reinterpret_cast<const float4*>(&g_cmp_v[n][t][4 * d4]);
        }
        __syncthreads();
#pragma unroll 4
        for (int tt = 0; tt < 32; ++tt) {
            int t = c * 32 + tt;
            float4 vv = *reinterpret_cast<const float4*>(kv + tt * KP + 4 * lane);
#pragma unroll
            for (int r = 0; r < TQ; ++r) {
                float p = scb[(h * 8 + r) * 128 + t];
                aC[r][0] = ffma2({p, p}, {vv.x, vv.y}, aC[r][0]);
                aC[r][1] = ffma2({p, p}, {vv.z, vv.w}, aC[r][1]);
            }
        }
        __syncthreads();
    }
#pragma unroll
    for (int r = 0; r < TQ; ++r) {
        float4 o4 = make_float4(aC[r][0].x, aC[r][0].y, aC[r][1].x, aC[r][1].y);
        *reinterpret_cast<float4*>(&g_cmp_o[s0 + r][n * GQA + h][4 * lane]) = o4;
    }

    // ---- D: p_slc + top-16 (warp = query) ----
    {
        int r = h;
        int s_r = s0 + r;
        int m = lane;
        float pm = 0.f;
        int tlo = 4 * m - 1; if (tlo < 0) tlo = 0;
        int thi = 4 * m + 3; if (thi > 127) thi = 127;
        for (int t = tlo; t <= thi; ++t) {
#pragma unroll
            for (int hh = 0; hh < 8; ++hh) pm += scb[(hh * 8 + r) * 128 + t];
        }
        int cur = s_r >> 6;
        bool forced = (m == 0) || (m == cur);
        bool causal = (m <= cur);
        float val = forced ? 1e30f : (causal ? pm : -1e30f);
        unsigned msk = 0;
        for (int it = 0; it < TOPN; ++it) {
            float bv = val;
            int bi = lane;
#pragma unroll
            for (int o = 16; o; o >>= 1) {
                float ov = __shfl_xor_sync(FULLMASK, bv, o);
                int oi = __shfl_xor_sync(FULLMASK, bi, o);
                if (ov > bv || (ov == bv && oi < bi)) { bv = ov; bi = oi; }
            }
            if (bv > -5e29f) msk |= (1u << bi);
            if (lane == bi) val = -INFINITY;
        }
        if (lane == 0) g_sel_mask[n][s_r] = msk;
    }
}

// ============================================================
// Kernel 3: main attention (R9 structure, legal aligned psm).
// K double-buffered, V single-buffered cp.async pipeline;
// max-free softmax; unified guarded PV; pitch-20 psm so p
// reads are single LDS.128 broadcasts.
// ============================================================
__global__ void __launch_bounds__(256, 2) k_main_attn(const float* __restrict__ q,
                                                      const float* __restrict__ kg,
                                                      const float* __restrict__ vg,
                                                      const float* __restrict__ wg,
                                                      const float* __restrict__ bg,
                                                      float* __restrict__ out) {
    extern __shared__ float sm[];
    float* qsm  = sm;                         // 8192
    float* ksm0 = sm + 8192;                  // 4224
    float* ksm1 = sm + 8192 + 4224;           // 4224
    float* vsm  = sm + 8192 + 8448;           // 4224
    float* psm  = sm + 8192 + 12672;          // 8*32*PSP = 5120
    int*   tli  = reinterpret_cast<int*>(sm + 8192 + 12672 + 5120);

    int s0 = (int)(gridDim.x - 1 - blockIdx.x) * TQ;  // long blocks first
    int n = blockIdx.y;
    int tid = threadIdx.x;
    int h = tid >> 5;
    int lane = tid & 31;
    int s_max = s0 + TQ - 1;

    int st_row = tid >> 5;
    int st_d4 = tid & 31;

    for (int u = tid; u < 2048; u += 256) {
        int qi = u >> 8, rem = u & 255, hh = rem >> 5, d4 = rem & 31;
        *reinterpret_cast<float4*>(qsm + (qi * 8 + hh) * 128 + 4 * d4) =
            *reinterpret_cast<const float4*>(
                q + ((size_t)(s0 + qi) * HQ + n * GQA + hh) * D + 4 * d4);
    }
    if (tid == 0) {
        unsigned orm = 0;
#pragma unroll
        for (int r = 0; r < TQ; ++r) {
            unsigned mk = g_sel_mask[n][s0 + r];
            tli[r] = (int)mk;
            orm |= mk;
        }
        int winlo0 = s0 - WIN; if (winlo0 < 0) winlo0 = 0;
        int cur_max = s_max >> 6;
        int c = 0;
        for (int b = 0; b <= cur_max; ++b) {
            bool anysel = (orm >> b) & 1u;
            for (int half = 0; half < 2; ++half) {
                int t0 = (b << 6) + half * 32;
                if (t0 > s_max) break;
                if (anysel || (t0 + 31 >= winlo0)) tli[8 + c++] = t0;
            }
        }
        tli[72] = c;
    }
    __syncthreads();
    int nt = tli[72];

    float lS[TQ], lW[TQ];
    float2 aS[TQ][2], aW[TQ][2];
#pragma unroll
    for (int r = 0; r < TQ; ++r) {
        lS[r] = 0.f; lW[r] = 0.f;
        aS[r][0] = {0.f, 0.f}; aS[r][1] = {0.f, 0.f};
        aW[r][0] = {0.f, 0.f}; aW[r][1] = {0.f, 0.f};
    }

    // ---- prologue: prefetch K(0) ----
    if (nt > 0) {
        int t0 = tli[8];
#pragma unroll
        for (int rr = 0; rr < 4; ++rr) {
            int row = st_row + 8 * rr;
            cp_async16(ksm0 + row * KP + 4 * st_d4,
                       kg + ((size_t)(t0 + row) * HK + n) * D + 4 * st_d4);
        }
    }
    CP_COMMIT();   // group: K(0)

    for (int i = 0; i < nt; ++i) {
        int t0 = tli[8 + i];
        float* kcur = (i & 1) ? ksm1 : ksm0;
        float* knxt = (i & 1) ? ksm0 : ksm1;
        bool hasnxt = (i + 1 < nt);

        __syncthreads();   // S1: vsm free (PV(i-1) done), knxt free

        // V(i) -> vsm  (own group)
#pragma unroll
        for (int rr = 0; rr < 4; ++rr) {
            int row = st_row + 8 * rr;
            cp_async16(vsm + row * KP + 4 * st_d4,
                       vg + ((size_t)(t0 + row) * HK + n) * D + 4 * st_d4);
        }
        CP_COMMIT();   // group: V(i)

        if (hasnxt) {
            int t0n = tli[8 + i + 1];
#pragma unroll
            for (int rr = 0; rr < 4; ++rr) {
                int row = st_row + 8 * rr;
                cp_async16(knxt + row * KP + 4 * st_d4,
                           kg + ((size_t)(t0n + row) * HK + n) * D + 4 * st_d4);
            }
            CP_COMMIT();   // group: K(i+1)
        }

        if (hasnxt) { CP_WAIT(2); } else { CP_WAIT(1); }   // K(i) complete
        __syncthreads();   // S2: K(i) visible

        // per-row flags (warp-uniform; identical across warps)
        int b = t0 >> 6;
        int selb = 0, winb = 0;
#pragma unroll
        for (int r = 0; r < TQ; ++r) {
            int s_r = s0 + r;
            int wl = s_r - WIN; if (wl < 0) wl = 0;
            bool ok = (t0 <= s_r);
            if (ok && (((unsigned)tli[r] >> b) & 1u)) selb |= 1 << r;
            if (ok && (t0 + 31 >= wl)) winb |= 1 << r;
        }
        int actb = selb | winb;
        int j = t0 + lane;

        // ---- scores ----
        float2 a2[TQ];
#pragma unroll
        for (int r = 0; r < TQ; ++r) a2[r] = make_float2(0.f, 0.f);
#pragma unroll 8
        for (int d4 = 0; d4 < 32; ++d4) {
            float4 kk = *reinterpret_cast<const float4*>(kcur + lane * KP + 4 * d4);
#pragma unroll
            for (int r = 0; r < TQ; ++r) {
                float4 qq = *reinterpret_cast<const float4*>(qsm + (r * 8 + h) * 128 + 4 * d4);
                a2[r] = ffma2({qq.x, qq.y}, {kk.x, kk.y}, a2[r]);
                a2[r] = ffma2({qq.z, qq.w}, {kk.z, kk.w}, a2[r]);
            }
        }

        // ---- max-free softmax; p -> psm (pitch 20, guarded writes) ----
#pragma unroll
        for (int r = 0; r < TQ; ++r) {
            if (!((actb >> r) & 1)) continue;
            int s_r = s0 + r;
            int wl = s_r - WIN; if (wl < 0) wl = 0;
            bool ins = (selb >> r) & 1;
            float sc = (a2[r].x + a2[r].y) * SCALE;
            bool contrib = (j <= s_r) && (ins || (j >= wl));
            float pe = contrib ? __expf(sc) : 0.f;
            float pS = ins ? pe : 0.f;
            float pW = (j >= wl) ? pe : 0.f;
            lS[r] += pS;
            lW[r] += pW;
            *reinterpret_cast<float2*>(psm + (h * 32 + lane) * PSP + 2 * r) =
                make_float2(pS, pW);
        }

        if (hasnxt) { CP_WAIT(1); } else { CP_WAIT(0); }   // V(i) complete
        __syncthreads();   // S3: V(i) visible (also orders psm writes->reads)

        // ---- PV: lane = d-quad; p via single aligned LDS.128 broadcast ----
#pragma unroll 4
        for (int tt = 0; tt < 32; ++tt) {
            float4 vv = *reinterpret_cast<const float4*>(vsm + tt * KP + 4 * lane);
            float2 va = {vv.x, vv.y}, vb = {vv.z, vv.w};
            const float* pb = psm + (h * 32 + tt) * PSP;
#pragma unroll
            for (int rp = 0; rp < 4; ++rp) {
                float4 pq = *reinterpret_cast<const float4*>(pb + 4 * rp);
                int r0 = 2 * rp, r1 = r0 + 1;
                if ((selb >> r0) & 1) {
                    aS[r0][0] = ffma2({pq.x, pq.x}, va, aS[r0][0]);
                    aS[r0][1] = ffma2({pq.x, pq.x}, vb, aS[r0][1]);
                }
                if ((winb >> r0) & 1) {
                    aW[r0][0] = ffma2({pq.y, pq.y}, va, aW[r0][0]);
                    aW[r0][1] = ffma2({pq.y, pq.y}, vb, aW[r0][1]);
                }
                if ((selb >> r1) & 1) {
                    aS[r1][0] = ffma2({pq.z, pq.z}, va, aS[r1][0]);
                    aS[r1][1] = ffma2({pq.z, pq.z}, vb, aS[r1][1]);
                }
                if ((winb >> r1) & 1) {
                    aW[r1][0] = ffma2({pq.w, pq.w}, va, aW[r1][0]);
                    aW[r1][1] = ffma2({pq.w, pq.w}, vb, aW[r1][1]);
                }
            }
        }
    }

    // ---- finalize: gates + combine (wg hoisted) ----
    float wgr[12];
#pragma unroll
    for (int i2 = 0; i2 < 12; ++i2) wgr[i2] = wg[(4 * lane) * 3 + i2];
    float bgr0 = bg[0], bgr1 = bg[1], bgr2 = bg[2];
#pragma unroll
    for (int r = 0; r < TQ; ++r) {
        int s_r = s0 + r;
        float4 q4 = *reinterpret_cast<const float4*>(qsm + (r * 8 + h) * 128 + 4 * lane);
        float gt[3];
#pragma unroll
        for (int c = 0; c < 3; ++c) {
            float gp = q4.x * wgr[0 + c] + q4.y * wgr[3 + c]
                     + q4.z * wgr[6 + c] + q4.w * wgr[9 + c];
            gp = warp_sum(gp) + (c == 0 ? bgr0 : (c == 1 ? bgr1 : bgr2));
            gt[c] = 1.f / (1.f + __expf(-gp));
        }
        float iS = 1.f / warp_sum(lS[r]);
        float iW = 1.f / warp_sum(lW[r]);
        float4 c4 = *reinterpret_cast<const float4*>(&g_cmp_o[s_r][n * GQA + h][4 * lane]);
        float4 o4;
        o4.x = c4.x * gt[0] + aS[r][0].x * iS * gt[1] + aW[r][0].x * iW * gt[2];
        o4.y = c4.y * gt[0] + aS[r][0].y * iS * gt[1] + aW[r][0].y * iW * gt[2];
        o4.z = c4.z * gt[0] + aS[r][1].x * iS * gt[1] + aW[r][1].x * iW * gt[2];
        o4.w = c4.w * gt[0] + aS[r][1].y * iS * gt[1] + aW[r][1].y * iW * gt[2];
        *reinterpret_cast<float4*>(out + ((size_t)s_r * HQ + n * GQA + h) * D + 4 * lane) = o4;
    }
}

// ============================================================
// launch  (inputs: q, k, v, w_cmp_k, w_cmp_v, w_gate, b_gate)
// ============================================================
extern "C" void kernel_launch(void* const* d_in, const int* in_sizes, int n_in,
                              void* d_out, int out_size) {
    const float* q   = (const float*)d_in[0];
    const float* k   = (const float*)d_in[1];
    const float* v   = (const float*)d_in[2];
    const float* wck = (const float*)d_in[3];
    const float* wcv = (const float*)d_in[4];
    const float* wg  = (const float*)d_in[5];
    const float* bg  = (const float*)d_in[6];
    float* out = (float*)d_out;

    const int smem2 = (8192 + 4224 + 8192) * 4;
    const int smem3 = (8192 + 4224 * 3 + 8 * 32 * PSP) * 4 + 73 * 4;
    cudaFuncSetAttribute(k_cmp_sel, cudaFuncAttributeMaxDynamicSharedMemorySize, smem2);
    cudaFuncSetAttribute(k_main_attn, cudaFuncAttributeMaxDynamicSharedMemorySize, smem3);

    k_compress<<<dim3(TBLK, HK), D>>>(k, v, wck, wcv);
    k_cmp_sel<<<dim3(S_LEN / TQ, HK), 256, smem2>>>(q);
    k_main_attn<<<dim3(S_LEN / TQ, HK), 256, smem3>>>(q, k, v, wg, bg, out);
}

// round 13
// speedup vs baseline: 1.0567x; 1.0077x over previous
#include <cuda_runtime.h>
#include <math.h>

// ---- NSA hyperparameters (fixed) ----
#define S_LEN 2048
#define HQ 16
#define HK 2
#define GQA 8
#define D 128
#define KS 32
#define ST 16
#define SEL 64
#define TOPN 16
#define WIN 512
#define TBLK 127
#define NSEL 32
#define TQ 8                        // queries per block (q-tile)
#define SCALE 0.08838834764831845f  // 1/sqrt(128)
#define SCL2E 0.12751771175711306f  // SCALE * log2(e)
#define FULLMASK 0xffffffffu
#define KP 132                      // smem K/V row pitch (floats)
#define PSP 20                      // psm pitch per (h,token) in floats (16B-aligned)

// ---- static device scratch ----
__device__ float    g_cmp_k[HK][TBLK][D];
__device__ float    g_cmp_v[HK][TBLK][D];
__device__ float    g_cmp_o[S_LEN][HQ][D];
__device__ unsigned g_sel_mask[HK][S_LEN];

__device__ __forceinline__ float warp_sum(float v) {
#pragma unroll
    for (int o = 16; o; o >>= 1) v += __shfl_xor_sync(FULLMASK, v, o);
    return v;
}
__device__ __forceinline__ float warp_max(float v) {
#pragma unroll
    for (int o = 16; o; o >>= 1) v = fmaxf(v, __shfl_xor_sync(FULLMASK, v, o));
    return v;
}
__device__ __forceinline__ float2 ffma2(float2 a, float2 b, float2 c) {
    unsigned long long au = *reinterpret_cast<unsigned long long*>(&a);
    unsigned long long bu = *reinterpret_cast<unsigned long long*>(&b);
    unsigned long long cu = *reinterpret_cast<unsigned long long*>(&c);
    unsigned long long du;
    asm("fma.rn.f32x2 %0, %1, %2, %3;" : "=l"(du) : "l"(au), "l"(bu), "l"(cu));
    return *reinterpret_cast<float2*>(&du);
}
__device__ __forceinline__ float ex2a(float x) {
    float r;
    asm("ex2.approx.f32 %0, %1;" : "=f"(r) : "f"(x));
    return r;
}
__device__ __forceinline__ void cp_async16(float* smem_dst, const float* gmem_src) {
    unsigned sa = (unsigned)__cvta_generic_to_shared(smem_dst);
    asm volatile("cp.async.cg.shared.global [%0], [%1], 16;\n" :: "r"(sa), "l"(gmem_src));
}
#define CP_COMMIT()  asm volatile("cp.async.commit_group;\n" ::: "memory")
#define CP_WAIT(N)   asm volatile("cp.async.wait_group %0;\n" :: "n"(N) : "memory")

// ============================================================
// Kernel 1: compressed K/V blocks
// ============================================================
__global__ void k_compress(const float* __restrict__ k,
                           const float* __restrict__ v,
                           const float* __restrict__ wck,
                           const float* __restrict__ wcv) {
    int t = blockIdx.x;
    int n = blockIdx.y;
    int d = threadIdx.x;
    float ak = 0.f, av = 0.f;
#pragma unroll
    for (int w = 0; w < KS; ++w) {
        int j = t * ST + w;
        size_t idx = ((size_t)j * HK + n) * D + d;
        ak += k[idx] * wck[w];
        av += v[idx] * wcv[w];
    }
    g_cmp_k[n][t][d] = ak;
    g_cmp_v[n][t][d] = av;
}

// ============================================================
// Kernel 2: compressed attention + selection, q-tiled.
// cp.async double-buffered K (phase A) and V (phase C) chunks;
// V0 prefetch overlapped with the softmax phase B.
// smem: qsm 8192 | kb0 4224 | kb1 4224 | scb 8192
// ============================================================
__global__ void __launch_bounds__(256) k_cmp_sel(const float* __restrict__ q) {
    extern __shared__ float sm[];
    float* qsm = sm;                    // 8192
    float* kb0 = sm + 8192;             // 4224
    float* kb1 = sm + 8192 + 4224;      // 4224
    float* scb = sm + 8192 + 8448;      // 8192

    int s0 = blockIdx.x * TQ;
    int n = blockIdx.y;
    int tid = threadIdx.x;
    int h = tid >> 5;
    int lane = tid & 31;

    int st_row = tid >> 5;     // rows h, h+8, h+16, h+24
    int st_d4 = tid & 31;

    for (int u = tid; u < 2048; u += 256) {
        int qi = u >> 8, rem = u & 255, hh = rem >> 5, d4 = rem & 31;
        *reinterpret_cast<float4*>(qsm + (qi * 8 + hh) * 128 + 4 * d4) =
            *reinterpret_cast<const float4*>(
                q + ((size_t)(s0 + qi) * HQ + n * GQA + hh) * D + 4 * d4);
    }
    int s_max = s0 + TQ - 1;
    int Tvm = (s_max >= KS - 1) ? (s_max - (KS - 1)) / ST + 1 : 0;
    int ct = (Tvm + 31) >> 5;

    // prologue: K chunk 0
    if (ct > 0) {
#pragma unroll
        for (int rr = 0; rr < 4; ++rr) {
            int row = st_row + 8 * rr;
            int t = row; if (t > TBLK - 1) t = TBLK - 1;
            cp_async16(kb0 + row * KP + 4 * st_d4, &g_cmp_k[n][t][4 * st_d4]);
        }
    }
    CP_COMMIT();   // group: K0

    // ---- A: raw scores (pipelined K chunks) ----
    for (int c = 0; c < ct; ++c) {
        float* kcur = (c & 1) ? kb1 : kb0;
        float* knxt = (c & 1) ? kb0 : kb1;
        __syncthreads();    // chunk c-1 readers done -> knxt free (c=0: no-op safety)
        if (c + 1 < ct) {
#pragma unroll
            for (int rr = 0; rr < 4; ++rr) {
                int row = st_row + 8 * rr;
                int t = (c + 1) * 32 + row; if (t > TBLK - 1) t = TBLK - 1;
                cp_async16(knxt + row * KP + 4 * st_d4, &g_cmp_k[n][t][4 * st_d4]);
            }
            CP_COMMIT();
            CP_WAIT(1);     // K(c) complete (K(c+1) may fly)
        } else {
            CP_WAIT(0);     // last: drain all
        }
        __syncthreads();    // K(c) + qsm visible

        float2 a2[TQ];
#pragma unroll
        for (int r = 0; r < TQ; ++r) a2[r] = make_float2(0.f, 0.f);
#pragma unroll 8
        for (int d4 = 0; d4 < 32; ++d4) {
            float4 kk = *reinterpret_cast<const float4*>(kcur + lane * KP + 4 * d4);
#pragma unroll
            for (int r = 0; r < TQ; ++r) {
                float4 qq = *reinterpret_cast<const float4*>(qsm + (r * 8 + h) * 128 + 4 * d4);
                a2[r] = ffma2({qq.x, qq.y}, {kk.x, kk.y}, a2[r]);
                a2[r] = ffma2({qq.z, qq.w}, {kk.z, kk.w}, a2[r]);
            }
        }
#pragma unroll
        for (int r = 0; r < TQ; ++r)
            scb[(h * 8 + r) * 128 + c * 32 + lane] = (a2[r].x + a2[r].y) * SCALE;
        // no trailing sync: scb rows warp-private
    }

    // prefetch V chunk 0 (overlaps with phase B)
    __syncthreads();        // last K chunk readers done -> kb0 free
    if (ct > 0) {
#pragma unroll
        for (int rr = 0; rr < 4; ++rr) {
            int row = st_row + 8 * rr;
            int t = row; if (t > TBLK - 1) t = TBLK - 1;
            cp_async16(kb0 + row * KP + 4 * st_d4, &g_cmp_v[n][t][4 * st_d4]);
        }
    }
    CP_COMMIT();   // group: V0

    // ---- B: per-row softmax (warp-private rows) ----
#pragma unroll
    for (int r = 0; r < TQ; ++r) {
        int s_r = s0 + r;
        int Tv = (s_r >= KS - 1) ? (s_r - (KS - 1)) / ST + 1 : 0;
        float* row = scb + (h * 8 + r) * 128;
        if (Tv == 0) {
            reinterpret_cast<float4*>(row)[lane] = make_float4(0.f, 0.f, 0.f, 0.f);
            continue;
        }
        float4 v4 = reinterpret_cast<float4*>(row)[lane];
        int tb = 4 * lane;
        float m = fmaxf(fmaxf(tb + 0 < Tv ? v4.x : -INFINITY, tb + 1 < Tv ? v4.y : -INFINITY),
                        fmaxf(tb + 2 < Tv ? v4.z : -INFINITY, tb + 3 < Tv ? v4.w : -INFINITY));
        m = warp_max(m);
        float e0 = tb + 0 < Tv ? __expf(v4.x - m) : 0.f;
        float e1 = tb + 1 < Tv ? __expf(v4.y - m) : 0.f;
        float e2 = tb + 2 < Tv ? __expf(v4.z - m) : 0.f;
        float e3 = tb + 3 < Tv ? __expf(v4.w - m) : 0.f;
        float l = warp_sum(e0 + e1 + e2 + e3);
        float inv = 1.f / l;
        reinterpret_cast<float4*>(row)[lane] =
            make_float4(e0 * inv, e1 * inv, e2 * inv, e3 * inv);
    }

    // ---- C: PV -> g_cmp_o (pipelined V chunks) ----
    float2 aC[TQ][2];
#pragma unroll
    for (int r = 0; r < TQ; ++r) { aC[r][0] = {0.f, 0.f}; aC[r][1] = {0.f, 0.f}; }
    for (int c = 0; c < ct; ++c) {
        float* vcur = (c & 1) ? kb1 : kb0;
        float* vnxt = (c & 1) ? kb0 : kb1;
        __syncthreads();    // chunk c-1 readers done -> vnxt free
        if (c + 1 < ct) {
#pragma unroll
            for (int rr = 0; rr < 4; ++rr) {
                int row = st_row + 8 * rr;
                int t = (c + 1) * 32 + row; if (t > TBLK - 1) t = TBLK - 1;
                cp_async16(vnxt + row * KP + 4 * st_d4, &g_cmp_v[n][t][4 * st_d4]);
            }
            CP_COMMIT();
            CP_WAIT(1);     // V(c) complete
        } else {
            CP_WAIT(0);
        }
        __syncthreads();    // V(c) visible

#pragma unroll 4
        for (int tt = 0; tt < 32; ++tt) {
            int t = c * 32 + tt;
            float4 vv = *reinterpret_cast<const float4*>(vcur + tt * KP + 4 * lane);
#pragma unroll
            for (int r = 0; r < TQ; ++r) {
                float p = scb[(h * 8 + r) * 128 + t];
                aC[r][0] = ffma2({p, p}, {vv.x, vv.y}, aC[r][0]);
                aC[r][1] = ffma2({p, p}, {vv.z, vv.w}, aC[r][1]);
            }
        }
    }
#pragma unroll
    for (int r = 0; r < TQ; ++r) {
        float4 o4 = make_float4(aC[r][0].x, aC[r][0].y, aC[r][1].x, aC[r][1].y);
        *reinterpret_cast<float4*>(&g_cmp_o[s0 + r][n * GQA + h][4 * lane]) = o4;
    }

    __syncthreads();   // all warps' scb (phase B) visible for cross-head reads in D

    // ---- D: p_slc + top-16 (warp = query; reads all heads' rows) ----
    {
        int r = h;
        int s_r = s0 + r;
        int m = lane;
        float pm = 0.f;
        int tlo = 4 * m - 1; if (tlo < 0) tlo = 0;
        int thi = 4 * m + 3; if (thi > 127) thi = 127;
        for (int t = tlo; t <= thi; ++t) {
#pragma unroll
            for (int hh = 0; hh < 8; ++hh) pm += scb[(hh * 8 + r) * 128 + t];
        }
        int cur = s_r >> 6;
        bool forced = (m == 0) || (m == cur);
        bool causal = (m <= cur);
        float val = forced ? 1e30f : (causal ? pm : -1e30f);
        unsigned msk = 0;
        for (int it = 0; it < TOPN; ++it) {
            float bv = val;
            int bi = lane;
#pragma unroll
            for (int o = 16; o; o >>= 1) {
                float ov = __shfl_xor_sync(FULLMASK, bv, o);
                int oi = __shfl_xor_sync(FULLMASK, bi, o);
                if (ov > bv || (ov == bv && oi < bi)) { bv = ov; bi = oi; }
            }
            if (bv > -5e29f) msk |= (1u << bi);
            if (lane == bi) val = -INFINITY;
        }
        if (lane == 0) g_sel_mask[n][s_r] = msk;
    }
}

// ============================================================
// Kernel 3: main attention (R12-proven structure).
// K double-buffered, V single-buffered cp.async pipeline;
// max-free softmax via single ex2; pitch-20 psm.
// ============================================================
__global__ void __launch_bounds__(256, 2) k_main_attn(const float* __restrict__ q,
                                                      const float* __restrict__ kg,
                                                      const float* __restrict__ vg,
                                                      const float* __restrict__ wg,
                                                      const float* __restrict__ bg,
                                                      float* __restrict__ out) {
    extern __shared__ float sm[];
    float* qsm  = sm;                         // 8192
    float* ksm0 = sm + 8192;                  // 4224
    float* ksm1 = sm + 8192 + 4224;           // 4224
    float* vsm  = sm + 8192 + 8448;           // 4224
    float* psm  = sm + 8192 + 12672;          // 8*32*PSP = 5120
    int*   tli  = reinterpret_cast<int*>(sm + 8192 + 12672 + 5120);

    int s0 = (int)(gridDim.x - 1 - blockIdx.x) * TQ;  // long blocks first
    int n = blockIdx.y;
    int tid = threadIdx.x;
    int h = tid >> 5;
    int lane = tid & 31;
    int s_max = s0 + TQ - 1;

    int st_row = tid >> 5;
    int st_d4 = tid & 31;

    for (int u = tid; u < 2048; u += 256) {
        int qi = u >> 8, rem = u & 255, hh = rem >> 5, d4 = rem & 31;
        *reinterpret_cast<float4*>(qsm + (qi * 8 + hh) * 128 + 4 * d4) =
            *reinterpret_cast<const float4*>(
                q + ((size_t)(s0 + qi) * HQ + n * GQA + hh) * D + 4 * d4);
    }
    if (tid == 0) {
        unsigned orm = 0;
#pragma unroll
        for (int r = 0; r < TQ; ++r) {
            unsigned mk = g_sel_mask[n][s0 + r];
            tli[r] = (int)mk;
            orm |= mk;
        }
        int winlo0 = s0 - WIN; if (winlo0 < 0) winlo0 = 0;
        int cur_max = s_max >> 6;
        int c = 0;
        for (int b = 0; b <= cur_max; ++b) {
            bool anysel = (orm >> b) & 1u;
            for (int half = 0; half < 2; ++half) {
                int t0 = (b << 6) + half * 32;
                if (t0 > s_max) break;
                if (anysel || (t0 + 31 >= winlo0)) tli[8 + c++] = t0;
            }
        }
        tli[72] = c;
    }
    __syncthreads();
    int nt = tli[72];

    float lS[TQ], lW[TQ];
    float2 aS[TQ][2], aW[TQ][2];
#pragma unroll
    for (int r = 0; r < TQ; ++r) {
        lS[r] = 0.f; lW[r] = 0.f;
        aS[r][0] = {0.f, 0.f}; aS[r][1] = {0.f, 0.f};
        aW[r][0] = {0.f, 0.f}; aW[r][1] = {0.f, 0.f};
    }

    // ---- prologue: prefetch K(0) ----
    if (nt > 0) {
        int t0 = tli[8];
#pragma unroll
        for (int rr = 0; rr < 4; ++rr) {
            int row = st_row + 8 * rr;
            cp_async16(ksm0 + row * KP + 4 * st_d4,
                       kg + ((size_t)(t0 + row) * HK + n) * D + 4 * st_d4);
        }
    }
    CP_COMMIT();   // group: K(0)

    for (int i = 0; i < nt; ++i) {
        int t0 = tli[8 + i];
        float* kcur = (i & 1) ? ksm1 : ksm0;
        float* knxt = (i & 1) ? ksm0 : ksm1;
        bool hasnxt = (i + 1 < nt);

        __syncthreads();   // S1: vsm free (PV(i-1) done), knxt free

        // V(i) -> vsm  (own group)
#pragma unroll
        for (int rr = 0; rr < 4; ++rr) {
            int row = st_row + 8 * rr;
            cp_async16(vsm + row * KP + 4 * st_d4,
                       vg + ((size_t)(t0 + row) * HK + n) * D + 4 * st_d4);
        }
        CP_COMMIT();   // group: V(i)

        if (hasnxt) {
            int t0n = tli[8 + i + 1];
#pragma unroll
            for (int rr = 0; rr < 4; ++rr) {
                int row = st_row + 8 * rr;
                cp_async16(knxt + row * KP + 4 * st_d4,
                           kg + ((size_t)(t0n + row) * HK + n) * D + 4 * st_d4);
            }
            CP_COMMIT();   // group: K(i+1)
        }

        if (hasnxt) { CP_WAIT(2); } else { CP_WAIT(1); }   // K(i) complete
        __syncthreads();   // S2: K(i) visible

        // per-row flags (warp-uniform; identical across warps)
        int b = t0 >> 6;
        int selb = 0, winb = 0;
#pragma unroll
        for (int r = 0; r < TQ; ++r) {
            int s_r = s0 + r;
            int wl = s_r - WIN; if (wl < 0) wl = 0;
            bool ok = (t0 <= s_r);
            if (ok && (((unsigned)tli[r] >> b) & 1u)) selb |= 1 << r;
            if (ok && (t0 + 31 >= wl)) winb |= 1 << r;
        }
        int actb = selb | winb;
        int j = t0 + lane;

        // ---- scores ----
        float2 a2[TQ];
#pragma unroll
        for (int r = 0; r < TQ; ++r) a2[r] = make_float2(0.f, 0.f);
#pragma unroll 8
        for (int d4 = 0; d4 < 32; ++d4) {
            float4 kk = *reinterpret_cast<const float4*>(kcur + lane * KP + 4 * d4);
#pragma unroll
            for (int r = 0; r < TQ; ++r) {
                float4 qq = *reinterpret_cast<const float4*>(qsm + (r * 8 + h) * 128 + 4 * d4);
                a2[r] = ffma2({qq.x, qq.y}, {kk.x, kk.y}, a2[r]);
                a2[r] = ffma2({qq.z, qq.w}, {kk.z, kk.w}, a2[r]);
            }
        }

        // ---- max-free softmax; p -> psm (pitch 20, guarded writes) ----
#pragma unroll
        for (int r = 0; r < TQ; ++r) {
            if (!((actb >> r) & 1)) continue;
            int s_r = s0 + r;
            int wl = s_r - WIN; if (wl < 0) wl = 0;
            bool ins = (selb >> r) & 1;
            bool contrib = (j <= s_r) && (ins || (j >= wl));
            float pe = contrib ? ex2a((a2[r].x + a2[r].y) * SCL2E) : 0.f;
            float pS = ins ? pe : 0.f;
            float pW = (j >= wl) ? pe : 0.f;
            lS[r] += pS;
            lW[r] += pW;
            *reinterpret_cast<float2*>(psm + (h * 32 + lane) * PSP + 2 * r) =
                make_float2(pS, pW);
        }

        if (hasnxt) { CP_WAIT(1); } else { CP_WAIT(0); }   // V(i) complete
        __syncthreads();   // S3: V(i) visible (also orders psm writes->reads)

        // ---- PV: lane = d-quad; p via single aligned LDS.128 broadcast ----
#pragma unroll 4
        for (int tt = 0; tt < 32; ++tt) {
            float4 vv = *reinterpret_cast<const float4*>(vsm + tt * KP + 4 * lane);
            float2 va = {vv.x, vv.y}, vb = {vv.z, vv.w};
            const float* pb = psm + (h * 32 + tt) * PSP;
#pragma unroll
            for (int rp = 0; rp < 4; ++rp) {
                float4 pq = *reinterpret_cast<const float4*>(pb + 4 * rp);
                int r0 = 2 * rp, r1 = r0 + 1;
                if ((selb >> r0) & 1) {
                    aS[r0][0] = ffma2({pq.x, pq.x}, va, aS[r0][0]);
                    aS[r0][1] = ffma2({pq.x, pq.x}, vb, aS[r0][1]);
                }
                if ((winb >> r0) & 1) {
                    aW[r0][0] = ffma2({pq.y, pq.y}, va, aW[r0][0]);
                    aW[r0][1] = ffma2({pq.y, pq.y}, vb, aW[r0][1]);
                }
                if ((selb >> r1) & 1) {
                    aS[r1][0] = ffma2({pq.z, pq.z}, va, aS[r1][0]);
                    aS[r1][1] = ffma2({pq.z, pq.z}, vb, aS[r1][1]);
                }
                if ((winb >> r1) & 1) {
                    aW[r1][0] = ffma2({pq.w, pq.w}, va, aW[r1][0]);
                    aW[r1][1] = ffma2({pq.w, pq.w}, vb, aW[r1][1]);
                }
            }
        }
    }

    // ---- finalize: gates + combine (wg hoisted) ----
    float wgr[12];
#pragma unroll
    for (int i2 = 0; i2 < 12; ++i2) wgr[i2] = wg[(4 * lane) * 3 + i2];
    float bgr0 = bg[0], bgr1 = bg[1], bgr2 = bg[2];
#pragma unroll
    for (int r = 0; r < TQ; ++r) {
        int s_r = s0 + r;
        float4 q4 = *reinterpret_cast<const float4*>(qsm + (r * 8 + h) * 128 + 4 * lane);
        float gt[3];
#pragma unroll
        for (int c = 0; c < 3; ++c) {
            float gp = q4.x * wgr[0 + c] + q4.y * wgr[3 + c]
                     + q4.z * wgr[6 + c] + q4.w * wgr[9 + c];
            gp = warp_sum(gp) + (c == 0 ? bgr0 : (c == 1 ? bgr1 : bgr2));
            gt[c] = 1.f / (1.f + __expf(-gp));
        }
        float iS = 1.f / warp_sum(lS[r]);
        float iW = 1.f / warp_sum(lW[r]);
        float4 c4 = *reinterpret_cast<const float4*>(&g_cmp_o[s_r][n * GQA + h][4 * lane]);
        float4 o4;
        o4.x = c4.x * gt[0] + aS[r][0].x * iS * gt[1] + aW[r][0].x * iW * gt[2];
        o4.y = c4.y * gt[0] + aS[r][0].y * iS * gt[1] + aW[r][0].y * iW * gt[2];
        o4.z = c4.z * gt[0] + aS[r][1].x * iS * gt[1] + aW[r][1].x * iW * gt[2];
        o4.w = c4.w * gt[0] + aS[r][1].y * iS * gt[1] + aW[r][1].y * iW * gt[2];
        *reinterpret_cast<float4*>(out + ((size_t)s_r * HQ + n * GQA + h) * D + 4 * lane) = o4;
    }
}

// ============================================================
// launch  (inputs: q, k, v, w_cmp_k, w_cmp_v, w_gate, b_gate)
// ============================================================
extern "C" void kernel_launch(void* const* d_in, const int* in_sizes, int n_in,
                              void* d_out, int out_size) {
    const float* q   = (const float*)d_in[0];
    const float* k   = (const float*)d_in[1];
    const float* v   = (const float*)d_in[2];
    const float* wck = (const float*)d_in[3];
    const float* wcv = (const float*)d_in[4];
    const float* wg  = (const float*)d_in[5];
    const float* bg  = (const float*)d_in[6];
    float* out = (float*)d_out;

    const int smem2 = (8192 + 2 * 4224 + 8192) * 4;
    const int smem3 = (8192 + 4224 * 3 + 8 * 32 * PSP) * 4 + 73 * 4;
    cudaFuncSetAttribute(k_cmp_sel, cudaFuncAttributeMaxDynamicSharedMemorySize, smem2);
    cudaFuncSetAttribute(k_main_attn, cudaFuncAttributeMaxDynamicSharedMemorySize, smem3);

    k_compress<<<dim3(TBLK, HK), D>>>(k, v, wck, wcv);
    k_cmp_sel<<<dim3(S_LEN / TQ, HK), 256, smem2>>>(q);
    k_main_attn<<<dim3(S_LEN / TQ, HK), 256, smem3>>>(q, k, v, wg, bg, out);
}

// round 14
// speedup vs baseline: 1.1453x; 1.0838x over previous
#include <cuda_runtime.h>
#include <math.h>

// ---- NSA hyperparameters (fixed) ----
#define S_LEN 2048
#define HQ 16
#define HK 2
#define GQA 8
#define D 128
#define KS 32
#define ST 16
#define SEL 64
#define TOPN 16
#define WIN 512
#define TBLK 127
#define NSEL 32
#define TQ 8                        // queries per block (q-tile)
#define SCALE 0.08838834764831845f  // 1/sqrt(128)
#define SCL2E 0.12751771175711306f  // SCALE * log2(e)
#define FULLMASK 0xffffffffu
#define KP 132                      // smem K/V row pitch (floats)
#define PSP 20                      // psm pitch per (h,token) in floats (16B-aligned)

// ---- static device scratch ----
__device__ float g_cmp_k[HK][TBLK][D];
__device__ float g_cmp_v[HK][TBLK][D];
__device__ float g_cmp_o[S_LEN][HQ][D];

__device__ __forceinline__ float warp_sum(float v) {
#pragma unroll
    for (int o = 16; o; o >>= 1) v += __shfl_xor_sync(FULLMASK, v, o);
    return v;
}
__device__ __forceinline__ float warp_max(float v) {
#pragma unroll
    for (int o = 16; o; o >>= 1) v = fmaxf(v, __shfl_xor_sync(FULLMASK, v, o));
    return v;
}
__device__ __forceinline__ float2 ffma2(float2 a, float2 b, float2 c) {
    unsigned long long au = *reinterpret_cast<unsigned long long*>(&a);
    unsigned long long bu = *reinterpret_cast<unsigned long long*>(&b);
    unsigned long long cu = *reinterpret_cast<unsigned long long*>(&c);
    unsigned long long du;
    asm("fma.rn.f32x2 %0, %1, %2, %3;" : "=l"(du) : "l"(au), "l"(bu), "l"(cu));
    return *reinterpret_cast<float2*>(&du);
}
__device__ __forceinline__ float ex2a(float x) {
    float r;
    asm("ex2.approx.f32 %0, %1;" : "=f"(r) : "f"(x));
    return r;
}
__device__ __forceinline__ void cp_async16(float* smem_dst, const float* gmem_src) {
    unsigned sa = (unsigned)__cvta_generic_to_shared(smem_dst);
    asm volatile("cp.async.cg.shared.global [%0], [%1], 16;\n" :: "r"(sa), "l"(gmem_src));
}
#define CP_COMMIT()  asm volatile("cp.async.commit_group;\n" ::: "memory")
#define CP_WAIT(N)   asm volatile("cp.async.wait_group %0;\n" :: "n"(N) : "memory")

// ============================================================
// Kernel 1: compressed K/V blocks
// ============================================================
__global__ void k_compress(const float* __restrict__ k,
                           const float* __restrict__ v,
                           const float* __restrict__ wck,
                           const float* __restrict__ wcv) {
    int t = blockIdx.x;
    int n = blockIdx.y;
    int d = threadIdx.x;
    float ak = 0.f, av = 0.f;
#pragma unroll
    for (int w = 0; w < KS; ++w) {
        int j = t * ST + w;
        size_t idx = ((size_t)j * HK + n) * D + d;
        ak += k[idx] * wck[w];
        av += v[idx] * wcv[w];
    }
    g_cmp_k[n][t][d] = ak;
    g_cmp_v[n][t][d] = av;
}

// ============================================================
// Fused kernel: cmp attention + selection + main attention.
// Block = (8 queries, kv-head n); 8 warps = 8 GQA heads.
// smem union: qsm | kb0/kb1 (cmp K/V bufs == main K bufs) |
//             regionB (scb for phases A-D, then vsm+psm) | tli
// ============================================================
__global__ void __launch_bounds__(256, 2) k_fused(const float* __restrict__ q,
                                                  const float* __restrict__ kg,
                                                  const float* __restrict__ vg,
                                                  const float* __restrict__ wg,
                                                  const float* __restrict__ bg,
                                                  float* __restrict__ out) {
    extern __shared__ float sm[];
    float* qsm = sm;                        // 8192
    float* kb0 = sm + 8192;                 // 4224
    float* kb1 = sm + 8192 + 4224;          // 4224
    float* scb = sm + 16640;                // 8192 (phases A-D)
    float* vsm = sm + 16640;                // 4224 (main loop)
    float* psm = sm + 16640 + 4224;         // 5120 (main loop)
    int*   tli = reinterpret_cast<int*>(sm + 25984);  // 73 ints

    int s0 = (int)(gridDim.x - 1 - blockIdx.x) * TQ;  // long blocks first
    int n = blockIdx.y;
    int tid = threadIdx.x;
    int h = tid >> 5;
    int lane = tid & 31;
    int s_max = s0 + TQ - 1;

    int st_row = tid >> 5;
    int st_d4 = tid & 31;

    // ---- q tile (loaded once for both stages) ----
    for (int u = tid; u < 2048; u += 256) {
        int qi = u >> 8, rem = u & 255, hh = rem >> 5, d4 = rem & 31;
        *reinterpret_cast<float4*>(qsm + (qi * 8 + hh) * 128 + 4 * d4) =
            *reinterpret_cast<const float4*>(
                q + ((size_t)(s0 + qi) * HQ + n * GQA + hh) * D + 4 * d4);
    }
    int Tvm = (s_max >= KS - 1) ? (s_max - (KS - 1)) / ST + 1 : 0;
    int ct = (Tvm + 31) >> 5;

    // prologue: cmp-K chunk 0
    if (ct > 0) {
#pragma unroll
        for (int rr = 0; rr < 4; ++rr) {
            int row = st_row + 8 * rr;
            int t = row; if (t > TBLK - 1) t = TBLK - 1;
            cp_async16(kb0 + row * KP + 4 * st_d4, &g_cmp_k[n][t][4 * st_d4]);
        }
    }
    CP_COMMIT();   // group: K0

    // ---- A: raw cmp scores (pipelined K chunks) ----
    for (int c = 0; c < ct; ++c) {
        float* kcur = (c & 1) ? kb1 : kb0;
        float* knxt = (c & 1) ? kb0 : kb1;
        __syncthreads();
        if (c + 1 < ct) {
#pragma unroll
            for (int rr = 0; rr < 4; ++rr) {
                int row = st_row + 8 * rr;
                int t = (c + 1) * 32 + row; if (t > TBLK - 1) t = TBLK - 1;
                cp_async16(knxt + row * KP + 4 * st_d4, &g_cmp_k[n][t][4 * st_d4]);
            }
            CP_COMMIT();
            CP_WAIT(1);
        } else {
            CP_WAIT(0);
        }
        __syncthreads();

        float2 a2[TQ];
#pragma unroll
        for (int r = 0; r < TQ; ++r) a2[r] = make_float2(0.f, 0.f);
#pragma unroll 8
        for (int d4 = 0; d4 < 32; ++d4) {
            float4 kk = *reinterpret_cast<const float4*>(kcur + lane * KP + 4 * d4);
#pragma unroll
            for (int r = 0; r < TQ; ++r) {
                float4 qq = *reinterpret_cast<const float4*>(qsm + (r * 8 + h) * 128 + 4 * d4);
                a2[r] = ffma2({qq.x, qq.y}, {kk.x, kk.y}, a2[r]);
                a2[r] = ffma2({qq.z, qq.w}, {kk.z, kk.w}, a2[r]);
            }
        }
#pragma unroll
        for (int r = 0; r < TQ; ++r)
            scb[(h * 8 + r) * 128 + c * 32 + lane] = (a2[r].x + a2[r].y) * SCALE;
    }

    // prefetch cmp-V chunk 0 (overlaps phase B)
    __syncthreads();
    if (ct > 0) {
#pragma unroll
        for (int rr = 0; rr < 4; ++rr) {
            int row = st_row + 8 * rr;
            int t = row; if (t > TBLK - 1) t = TBLK - 1;
            cp_async16(kb0 + row * KP + 4 * st_d4, &g_cmp_v[n][t][4 * st_d4]);
        }
    }
    CP_COMMIT();   // group: V0

    // ---- B: per-row softmax (warp-private rows) ----
#pragma unroll
    for (int r = 0; r < TQ; ++r) {
        int s_r = s0 + r;
        int Tv = (s_r >= KS - 1) ? (s_r - (KS - 1)) / ST + 1 : 0;
        float* row = scb + (h * 8 + r) * 128;
        if (Tv == 0) {
            reinterpret_cast<float4*>(row)[lane] = make_float4(0.f, 0.f, 0.f, 0.f);
            continue;
        }
        float4 v4 = reinterpret_cast<float4*>(row)[lane];
        int tb = 4 * lane;
        float m = fmaxf(fmaxf(tb + 0 < Tv ? v4.x : -INFINITY, tb + 1 < Tv ? v4.y : -INFINITY),
                        fmaxf(tb + 2 < Tv ? v4.z : -INFINITY, tb + 3 < Tv ? v4.w : -INFINITY));
        m = warp_max(m);
        float e0 = tb + 0 < Tv ? __expf(v4.x - m) : 0.f;
        float e1 = tb + 1 < Tv ? __expf(v4.y - m) : 0.f;
        float e2 = tb + 2 < Tv ? __expf(v4.z - m) : 0.f;
        float e3 = tb + 3 < Tv ? __expf(v4.w - m) : 0.f;
        float l = warp_sum(e0 + e1 + e2 + e3);
        float inv = 1.f / l;
        reinterpret_cast<float4*>(row)[lane] =
            make_float4(e0 * inv, e1 * inv, e2 * inv, e3 * inv);
    }

    // ---- C: cmp PV -> g_cmp_o (pipelined V chunks) ----
    {
        float2 aC[TQ][2];
#pragma unroll
        for (int r = 0; r < TQ; ++r) { aC[r][0] = {0.f, 0.f}; aC[r][1] = {0.f, 0.f}; }
        for (int c = 0; c < ct; ++c) {
            float* vcur = (c & 1) ? kb1 : kb0;
            float* vnxt = (c & 1) ? kb0 : kb1;
            __syncthreads();
            if (c + 1 < ct) {
#pragma unroll
                for (int rr = 0; rr < 4; ++rr) {
                    int row = st_row + 8 * rr;
                    int t = (c + 1) * 32 + row; if (t > TBLK - 1) t = TBLK - 1;
                    cp_async16(vnxt + row * KP + 4 * st_d4, &g_cmp_v[n][t][4 * st_d4]);
                }
                CP_COMMIT();
                CP_WAIT(1);
            } else {
                CP_WAIT(0);
            }
            __syncthreads();

#pragma unroll 4
            for (int tt = 0; tt < 32; ++tt) {
                int t = c * 32 + tt;
                float4 vv = *reinterpret_cast<const float4*>(vcur + tt * KP + 4 * lane);
#pragma unroll
                for (int r = 0; r < TQ; ++r) {
                    float p = scb[(h * 8 + r) * 128 + t];
                    aC[r][0] = ffma2({p, p}, {vv.x, vv.y}, aC[r][0]);
                    aC[r][1] = ffma2({p, p}, {vv.z, vv.w}, aC[r][1]);
                }
            }
        }
#pragma unroll
        for (int r = 0; r < TQ; ++r) {
            float4 o4 = make_float4(aC[r][0].x, aC[r][0].y, aC[r][1].x, aC[r][1].y);
            *reinterpret_cast<float4*>(&g_cmp_o[s0 + r][n * GQA + h][4 * lane]) = o4;
        }
    }
    CP_WAIT(0);        // clean group count for the main-loop pipeline
    __syncthreads();   // all scb(B) visible for cross-head reads in D

    // ---- D: p_slc + top-16 (warp = query r=h); mask -> tli[h] ----
    {
        int r = h;
        int s_r = s0 + r;
        int m = lane;
        float pm = 0.f;
        int tlo = 4 * m - 1; if (tlo < 0) tlo = 0;
        int thi = 4 * m + 3; if (thi > 127) thi = 127;
        for (int t = tlo; t <= thi; ++t) {
#pragma unroll
            for (int hh = 0; hh < 8; ++hh) pm += scb[(hh * 8 + r) * 128 + t];
        }
        int cur = s_r >> 6;
        bool forced = (m == 0) || (m == cur);
        bool causal = (m <= cur);
        float val = forced ? 1e30f : (causal ? pm : -1e30f);
        unsigned msk = 0;
        for (int it = 0; it < TOPN; ++it) {
            float bv = val;
            int bi = lane;
#pragma unroll
            for (int o = 16; o; o >>= 1) {
                float ov = __shfl_xor_sync(FULLMASK, bv, o);
                int oi = __shfl_xor_sync(FULLMASK, bi, o);
                if (ov > bv || (ov == bv && oi < bi)) { bv = ov; bi = oi; }
            }
            if (bv > -5e29f) msk |= (1u << bi);
            if (lane == bi) val = -INFINITY;
        }
        if (lane == 0) tli[h] = (int)msk;
    }
    __syncthreads();   // tli[0..7] ready; scb no longer needed

    // ---- tile list (tid 0) ----
    if (tid == 0) {
        unsigned orm = 0;
#pragma unroll
        for (int r = 0; r < TQ; ++r) orm |= (unsigned)tli[r];
        int winlo0 = s0 - WIN; if (winlo0 < 0) winlo0 = 0;
        int cur_max = s_max >> 6;
        int c = 0;
        for (int b = 0; b <= cur_max; ++b) {
            bool anysel = (orm >> b) & 1u;
            for (int half = 0; half < 2; ++half) {
                int t0 = (b << 6) + half * 32;
                if (t0 > s_max) break;
                if (anysel || (t0 + 31 >= winlo0)) tli[8 + c++] = t0;
            }
        }
        tli[72] = c;
    }
    __syncthreads();
    int nt = tli[72];

    float lS[TQ], lW[TQ];
    float2 aS[TQ][2], aW[TQ][2];
#pragma unroll
    for (int r = 0; r < TQ; ++r) {
        lS[r] = 0.f; lW[r] = 0.f;
        aS[r][0] = {0.f, 0.f}; aS[r][1] = {0.f, 0.f};
        aW[r][0] = {0.f, 0.f}; aW[r][1] = {0.f, 0.f};
    }

    // ---- main prologue: prefetch K(0) ----
    if (nt > 0) {
        int t0 = tli[8];
#pragma unroll
        for (int rr = 0; rr < 4; ++rr) {
            int row = st_row + 8 * rr;
            cp_async16(kb0 + row * KP + 4 * st_d4,
                       kg + ((size_t)(t0 + row) * HK + n) * D + 4 * st_d4);
        }
    }
    CP_COMMIT();   // group: K(0)

    for (int i = 0; i < nt; ++i) {
        int t0 = tli[8 + i];
        float* kcur = (i & 1) ? kb1 : kb0;
        float* knxt = (i & 1) ? kb0 : kb1;
        bool hasnxt = (i + 1 < nt);

        __syncthreads();   // S1: vsm free (PV(i-1) done), knxt free

        // V(i) -> vsm  (own group)
#pragma unroll
        for (int rr = 0; rr < 4; ++rr) {
            int row = st_row + 8 * rr;
            cp_async16(vsm + row * KP + 4 * st_d4,
                       vg + ((size_t)(t0 + row) * HK + n) * D + 4 * st_d4);
        }
        CP_COMMIT();   // group: V(i)

        if (hasnxt) {
            int t0n = tli[8 + i + 1];
#pragma unroll
            for (int rr = 0; rr < 4; ++rr) {
                int row = st_row + 8 * rr;
                cp_async16(knxt + row * KP + 4 * st_d4,
                           kg + ((size_t)(t0n + row) * HK + n) * D + 4 * st_d4);
            }
            CP_COMMIT();   // group: K(i+1)
        }

        if (hasnxt) { CP_WAIT(2); } else { CP_WAIT(1); }   // K(i) complete
        __syncthreads();   // S2: K(i) visible

        // per-row flags (warp-uniform; identical across warps)
        int b = t0 >> 6;
        int selb = 0, winb = 0;
#pragma unroll
        for (int r = 0; r < TQ; ++r) {
            int s_r = s0 + r;
            int wl = s_r - WIN; if (wl < 0) wl = 0;
            bool ok = (t0 <= s_r);
            if (ok && (((unsigned)tli[r] >> b) & 1u)) selb |= 1 << r;
            if (ok && (t0 + 31 >= wl)) winb |= 1 << r;
        }
        int actb = selb | winb;
        int j = t0 + lane;

        // ---- scores ----
        float2 a2[TQ];
#pragma unroll
        for (int r = 0; r < TQ; ++r) a2[r] = make_float2(0.f, 0.f);
#pragma unroll 8
        for (int d4 = 0; d4 < 32; ++d4) {
            float4 kk = *reinterpret_cast<const float4*>(kcur + lane * KP + 4 * d4);
#pragma unroll
            for (int r = 0; r < TQ; ++r) {
                float4 qq = *reinterpret_cast<const float4*>(qsm + (r * 8 + h) * 128 + 4 * d4);
                a2[r] = ffma2({qq.x, qq.y}, {kk.x, kk.y}, a2[r]);
                a2[r] = ffma2({qq.z, qq.w}, {kk.z, kk.w}, a2[r]);
            }
        }

        // ---- max-free softmax; p -> psm (pitch 20, guarded writes) ----
#pragma unroll
        for (int r = 0; r < TQ; ++r) {
            if (!((actb >> r) & 1)) continue;
            int s_r = s0 + r;
            int wl = s_r - WIN; if (wl < 0) wl = 0;
            bool ins = (selb >> r) & 1;
            bool contrib = (j <= s_r) && (ins || (j >= wl));
            float pe = contrib ? ex2a((a2[r].x + a2[r].y) * SCL2E) : 0.f;
            float pS = ins ? pe : 0.f;
            float pW = (j >= wl) ? pe : 0.f;
            lS[r] += pS;
            lW[r] += pW;
            *reinterpret_cast<float2*>(psm + (h * 32 + lane) * PSP + 2 * r) =
                make_float2(pS, pW);
        }

        if (hasnxt) { CP_WAIT(1); } else { CP_WAIT(0); }   // V(i) complete
        __syncthreads();   // S3: V(i) visible (also orders psm writes->reads)

        // ---- PV: lane = d-quad; p via single aligned LDS.128 broadcast ----
#pragma unroll 4
        for (int tt = 0; tt < 32; ++tt) {
            float4 vv = *reinterpret_cast<const float4*>(vsm + tt * KP + 4 * lane);
            float2 va = {vv.x, vv.y}, vb = {vv.z, vv.w};
            const float* pb = psm + (h * 32 + tt) * PSP;
#pragma unroll
            for (int rp = 0; rp < 4; ++rp) {
                float4 pq = *reinterpret_cast<const float4*>(pb + 4 * rp);
                int r0 = 2 * rp, r1 = r0 + 1;
                if ((selb >> r0) & 1) {
                    aS[r0][0] = ffma2({pq.x, pq.x}, va, aS[r0][0]);
                    aS[r0][1] = ffma2({pq.x, pq.x}, vb, aS[r0][1]);
                }
                if ((winb >> r0) & 1) {
                    aW[r0][0] = ffma2({pq.y, pq.y}, va, aW[r0][0]);
                    aW[r0][1] = ffma2({pq.y, pq.y}, vb, aW[r0][1]);
                }
                if ((selb >> r1) & 1) {
                    aS[r1][0] = ffma2({pq.z, pq.z}, va, aS[r1][0]);
                    aS[r1][1] = ffma2({pq.z, pq.z}, vb, aS[r1][1]);
                }
                if ((winb >> r1) & 1) {
                    aW[r1][0] = ffma2({pq.w, pq.w}, va, aW[r1][0]);
                    aW[r1][1] = ffma2({pq.w, pq.w}, vb, aW[r1][1]);
                }
            }
        }
    }

    // ---- finalize: gates + combine (wg hoisted) ----
    float wgr[12];
#pragma unroll
    for (int i2 = 0; i2 < 12; ++i2) wgr[i2] = wg[(4 * lane) * 3 + i2];
    float bgr0 = bg[0], bgr1 = bg[1], bgr2 = bg[2];
#pragma unroll
    for (int r = 0; r < TQ; ++r) {
        int s_r = s0 + r;
        float4 q4 = *reinterpret_cast<const float4*>(qsm + (r * 8 + h) * 128 + 4 * lane);
        float gt[3];
#pragma unroll
        for (int c = 0; c < 3; ++c) {
            float gp = q4.x * wgr[0 + c] + q4.y * wgr[3 + c]
                     + q4.z * wgr[6 + c] + q4.w * wgr[9 + c];
            gp = warp_sum(gp) + (c == 0 ? bgr0 : (c == 1 ? bgr1 : bgr2));
            gt[c] = 1.f / (1.f + __expf(-gp));
        }
        float iS = 1.f / warp_sum(lS[r]);
        float iW = 1.f / warp_sum(lW[r]);
        float4 c4 = *reinterpret_cast<const float4*>(&g_cmp_o[s_r][n * GQA + h][4 * lane]);
        float4 o4;
        o4.x = c4.x * gt[0] + aS[r][0].x * iS * gt[1] + aW[r][0].x * iW * gt[2];
        o4.y = c4.y * gt[0] + aS[r][0].y * iS * gt[1] + aW[r][0].y * iW * gt[2];
        o4.z = c4.z * gt[0] + aS[r][1].x * iS * gt[1] + aW[r][1].x * iW * gt[2];
        o4.w = c4.w * gt[0] + aS[r][1].y * iS * gt[1] + aW[r][1].y * iW * gt[2];
        *reinterpret_cast<float4*>(out + ((size_t)s_r * HQ + n * GQA + h) * D + 4 * lane) = o4;
    }
}

// ============================================================
// launch  (inputs: q, k, v, w_cmp_k, w_cmp_v, w_gate, b_gate)
// ============================================================
extern "C" void kernel_launch(void* const* d_in, const int* in_sizes, int n_in,
                              void* d_out, int out_size) {
    const float* q   = (const float*)d_in[0];
    const float* k   = (const float*)d_in[1];
    const float* v   = (const float*)d_in[2];
    const float* wck = (const float*)d_in[3];
    const float* wcv = (const float*)d_in[4];
    const float* wg  = (const float*)d_in[5];
    const float* bg  = (const float*)d_in[6];
    float* out = (float*)d_out;

    const int smemF = (8192 + 2 * 4224 + 4224 + 5120) * 4 + 73 * 4;
    cudaFuncSetAttribute(k_fused, cudaFuncAttributeMaxDynamicSharedMemorySize, smemF);

    k_compress<<<dim3(TBLK, HK), D>>>(k, v, wck, wcv);
    k_fused<<<dim3(S_LEN / TQ, HK), 256, smemF>>>(q, k, v, wg, bg, out);
}

// round 15
// speedup vs baseline: 1.1481x; 1.0025x over previous
#include <cuda_runtime.h>
#include <math.h>

// ---- NSA hyperparameters (fixed) ----
#define S_LEN 2048
#define HQ 16
#define HK 2
#define GQA 8
#define D 128
#define KS 32
#define ST 16
#define SEL 64
#define TOPN 16
#define WIN 512
#define TBLK 127
#define NSEL 32
#define TQ 8                        // queries per block (q-tile)
#define SCALE 0.08838834764831845f  // 1/sqrt(128)
#define SCL2E 0.12751771175711306f  // SCALE * log2(e)
#define L2E 1.4426950408889634f
#define FULLMASK 0xffffffffu
#define KP 132                      // smem K/V row pitch (floats)
#define PSP 20                      // psm pitch per (h,token) in floats (16B-aligned)

// ---- static device scratch ----
__device__ float g_cmp_k[HK][TBLK][D];
__device__ float g_cmp_v[HK][TBLK][D];
__device__ float g_cmp_o[S_LEN][HQ][D];

__device__ __forceinline__ float warp_sum(float v) {
#pragma unroll
    for (int o = 16; o; o >>= 1) v += __shfl_xor_sync(FULLMASK, v, o);
    return v;
}
__device__ __forceinline__ float warp_max(float v) {
#pragma unroll
    for (int o = 16; o; o >>= 1) v = fmaxf(v, __shfl_xor_sync(FULLMASK, v, o));
    return v;
}
__device__ __forceinline__ float2 ffma2(float2 a, float2 b, float2 c) {
    unsigned long long au = *reinterpret_cast<unsigned long long*>(&a);
    unsigned long long bu = *reinterpret_cast<unsigned long long*>(&b);
    unsigned long long cu = *reinterpret_cast<unsigned long long*>(&c);
    unsigned long long du;
    asm("fma.rn.f32x2 %0, %1, %2, %3;" : "=l"(du) : "l"(au), "l"(bu), "l"(cu));
    return *reinterpret_cast<float2*>(&du);
}
__device__ __forceinline__ float ex2a(float x) {
    float r;
    asm("ex2.approx.f32 %0, %1;" : "=f"(r) : "f"(x));
    return r;
}
__device__ __forceinline__ void cp_async16(float* smem_dst, const float* gmem_src) {
    unsigned sa = (unsigned)__cvta_generic_to_shared(smem_dst);
    asm volatile("cp.async.cg.shared.global [%0], [%1], 16;\n" :: "r"(sa), "l"(gmem_src));
}
#define CP_COMMIT()  asm volatile("cp.async.commit_group;\n" ::: "memory")
#define CP_WAIT(N)   asm volatile("cp.async.wait_group %0;\n" :: "n"(N) : "memory")

// ============================================================
// Kernel 1: compressed K/V blocks
// ============================================================
__global__ void k_compress(const float* __restrict__ k,
                           const float* __restrict__ v,
                           const float* __restrict__ wck,
                           const float* __restrict__ wcv) {
    int t = blockIdx.x;
    int n = blockIdx.y;
    int d = threadIdx.x;
    float ak = 0.f, av = 0.f;
#pragma unroll
    for (int w = 0; w < KS; ++w) {
        int j = t * ST + w;
        size_t idx = ((size_t)j * HK + n) * D + d;
        ak += k[idx] * wck[w];
        av += v[idx] * wcv[w];
    }
    g_cmp_k[n][t][d] = ak;
    g_cmp_v[n][t][d] = av;
}

// ============================================================
// Fused kernel: cmp attention + selection + main attention.
// (R14-proven structure; scores now predicated on per-row
//  activity, gates via ex2.approx)
// ============================================================
__global__ void __launch_bounds__(256, 2) k_fused(const float* __restrict__ q,
                                                  const float* __restrict__ kg,
                                                  const float* __restrict__ vg,
                                                  const float* __restrict__ wg,
                                                  const float* __restrict__ bg,
                                                  float* __restrict__ out) {
    extern __shared__ float sm[];
    float* qsm = sm;                        // 8192
    float* kb0 = sm + 8192;                 // 4224
    float* kb1 = sm + 8192 + 4224;          // 4224
    float* scb = sm + 16640;                // 8192 (phases A-D)
    float* vsm = sm + 16640;                // 4224 (main loop)
    float* psm = sm + 16640 + 4224;         // 5120 (main loop)
    int*   tli = reinterpret_cast<int*>(sm + 25984);  // 73 ints

    int s0 = (int)(gridDim.x - 1 - blockIdx.x) * TQ;  // long blocks first
    int n = blockIdx.y;
    int tid = threadIdx.x;
    int h = tid >> 5;
    int lane = tid & 31;
    int s_max = s0 + TQ - 1;

    int st_row = tid >> 5;
    int st_d4 = tid & 31;

    // ---- q tile (loaded once for both stages) ----
    for (int u = tid; u < 2048; u += 256) {
        int qi = u >> 8, rem = u & 255, hh = rem >> 5, d4 = rem & 31;
        *reinterpret_cast<float4*>(qsm + (qi * 8 + hh) * 128 + 4 * d4) =
            *reinterpret_cast<const float4*>(
                q + ((size_t)(s0 + qi) * HQ + n * GQA + hh) * D + 4 * d4);
    }
    int Tvm = (s_max >= KS - 1) ? (s_max - (KS - 1)) / ST + 1 : 0;
    int ct = (Tvm + 31) >> 5;

    // prologue: cmp-K chunk 0
    if (ct > 0) {
#pragma unroll
        for (int rr = 0; rr < 4; ++rr) {
            int row = st_row + 8 * rr;
            int t = row; if (t > TBLK - 1) t = TBLK - 1;
            cp_async16(kb0 + row * KP + 4 * st_d4, &g_cmp_k[n][t][4 * st_d4]);
        }
    }
    CP_COMMIT();   // group: K0

    // ---- A: raw cmp scores (pipelined K chunks) ----
    for (int c = 0; c < ct; ++c) {
        float* kcur = (c & 1) ? kb1 : kb0;
        float* knxt = (c & 1) ? kb0 : kb1;
        __syncthreads();
        if (c + 1 < ct) {
#pragma unroll
            for (int rr = 0; rr < 4; ++rr) {
                int row = st_row + 8 * rr;
                int t = (c + 1) * 32 + row; if (t > TBLK - 1) t = TBLK - 1;
                cp_async16(knxt + row * KP + 4 * st_d4, &g_cmp_k[n][t][4 * st_d4]);
            }
            CP_COMMIT();
            CP_WAIT(1);
        } else {
            CP_WAIT(0);
        }
        __syncthreads();

        float2 a2[TQ];
#pragma unroll
        for (int r = 0; r < TQ; ++r) a2[r] = make_float2(0.f, 0.f);
#pragma unroll 8
        for (int d4 = 0; d4 < 32; ++d4) {
            float4 kk = *reinterpret_cast<const float4*>(kcur + lane * KP + 4 * d4);
#pragma unroll
            for (int r = 0; r < TQ; ++r) {
                float4 qq = *reinterpret_cast<const float4*>(qsm + (r * 8 + h) * 128 + 4 * d4);
                a2[r] = ffma2({qq.x, qq.y}, {kk.x, kk.y}, a2[r]);
                a2[r] = ffma2({qq.z, qq.w}, {kk.z, kk.w}, a2[r]);
            }
        }
#pragma unroll
        for (int r = 0; r < TQ; ++r)
            scb[(h * 8 + r) * 128 + c * 32 + lane] = (a2[r].x + a2[r].y) * SCALE;
    }

    // prefetch cmp-V chunk 0 (overlaps phase B)
    __syncthreads();
    if (ct > 0) {
#pragma unroll
        for (int rr = 0; rr < 4; ++rr) {
            int row = st_row + 8 * rr;
            int t = row; if (t > TBLK - 1) t = TBLK - 1;
            cp_async16(kb0 + row * KP + 4 * st_d4, &g_cmp_v[n][t][4 * st_d4]);
        }
    }
    CP_COMMIT();   // group: V0

    // ---- B: per-row softmax (warp-private rows) ----
#pragma unroll
    for (int r = 0; r < TQ; ++r) {
        int s_r = s0 + r;
        int Tv = (s_r >= KS - 1) ? (s_r - (KS - 1)) / ST + 1 : 0;
        float* row = scb + (h * 8 + r) * 128;
        if (Tv == 0) {
            reinterpret_cast<float4*>(row)[lane] = make_float4(0.f, 0.f, 0.f, 0.f);
            continue;
        }
        float4 v4 = reinterpret_cast<float4*>(row)[lane];
        int tb = 4 * lane;
        float m = fmaxf(fmaxf(tb + 0 < Tv ? v4.x : -INFINITY, tb + 1 < Tv ? v4.y : -INFINITY),
                        fmaxf(tb + 2 < Tv ? v4.z : -INFINITY, tb + 3 < Tv ? v4.w : -INFINITY));
        m = warp_max(m);
        float e0 = tb + 0 < Tv ? __expf(v4.x - m) : 0.f;
        float e1 = tb + 1 < Tv ? __expf(v4.y - m) : 0.f;
        float e2 = tb + 2 < Tv ? __expf(v4.z - m) : 0.f;
        float e3 = tb + 3 < Tv ? __expf(v4.w - m) : 0.f;
        float l = warp_sum(e0 + e1 + e2 + e3);
        float inv = 1.f / l;
        reinterpret_cast<float4*>(row)[lane] =
            make_float4(e0 * inv, e1 * inv, e2 * inv, e3 * inv);
    }

    // ---- C: cmp PV -> g_cmp_o (pipelined V chunks) ----
    {
        float2 aC[TQ][2];
#pragma unroll
        for (int r = 0; r < TQ; ++r) { aC[r][0] = {0.f, 0.f}; aC[r][1] = {0.f, 0.f}; }
        for (int c = 0; c < ct; ++c) {
            float* vcur = (c & 1) ? kb1 : kb0;
            float* vnxt = (c & 1) ? kb0 : kb1;
            __syncthreads();
            if (c + 1 < ct) {
#pragma unroll
                for (int rr = 0; rr < 4; ++rr) {
                    int row = st_row + 8 * rr;
                    int t = (c + 1) * 32 + row; if (t > TBLK - 1) t = TBLK - 1;
                    cp_async16(vnxt + row * KP + 4 * st_d4, &g_cmp_v[n][t][4 * st_d4]);
                }
                CP_COMMIT();
                CP_WAIT(1);
            } else {
                CP_WAIT(0);
            }
            __syncthreads();

#pragma unroll 4
            for (int tt = 0; tt < 32; ++tt) {
                int t = c * 32 + tt;
                float4 vv = *reinterpret_cast<const float4*>(vcur + tt * KP + 4 * lane);
#pragma unroll
                for (int r = 0; r < TQ; ++r) {
                    float p = scb[(h * 8 + r) * 128 + t];
                    aC[r][0] = ffma2({p, p}, {vv.x, vv.y}, aC[r][0]);
                    aC[r][1] = ffma2({p, p}, {vv.z, vv.w}, aC[r][1]);
                }
            }
        }
#pragma unroll
        for (int r = 0; r < TQ; ++r) {
            float4 o4 = make_float4(aC[r][0].x, aC[r][0].y, aC[r][1].x, aC[r][1].y);
            *reinterpret_cast<float4*>(&g_cmp_o[s0 + r][n * GQA + h][4 * lane]) = o4;
        }
    }
    CP_WAIT(0);        // clean group count for the main-loop pipeline
    __syncthreads();   // all scb(B) visible for cross-head reads in D

    // ---- D: p_slc + top-16 (warp = query r=h); mask -> tli[h] ----
    {
        int r = h;
        int s_r = s0 + r;
        int m = lane;
        float pm = 0.f;
        int tlo = 4 * m - 1; if (tlo < 0) tlo = 0;
        int thi = 4 * m + 3; if (thi > 127) thi = 127;
        for (int t = tlo; t <= thi; ++t) {
#pragma unroll
            for (int hh = 0; hh < 8; ++hh) pm += scb[(hh * 8 + r) * 128 + t];
        }
        int cur = s_r >> 6;
        bool forced = (m == 0) || (m == cur);
        bool causal = (m <= cur);
        float val = forced ? 1e30f : (causal ? pm : -1e30f);
        unsigned msk = 0;
        for (int it = 0; it < TOPN; ++it) {
            float bv = val;
            int bi = lane;
#pragma unroll
            for (int o = 16; o; o >>= 1) {
                float ov = __shfl_xor_sync(FULLMASK, bv, o);
                int oi = __shfl_xor_sync(FULLMASK, bi, o);
                if (ov > bv || (ov == bv && oi < bi)) { bv = ov; bi = oi; }
            }
            if (bv > -5e29f) msk |= (1u << bi);
            if (lane == bi) val = -INFINITY;
        }
        if (lane == 0) tli[h] = (int)msk;
    }
    __syncthreads();   // tli[0..7] ready; scb no longer needed

    // ---- tile list (tid 0) ----
    if (tid == 0) {
        unsigned orm = 0;
#pragma unroll
        for (int r = 0; r < TQ; ++r) orm |= (unsigned)tli[r];
        int winlo0 = s0 - WIN; if (winlo0 < 0) winlo0 = 0;
        int cur_max = s_max >> 6;
        int c = 0;
        for (int b = 0; b <= cur_max; ++b) {
            bool anysel = (orm >> b) & 1u;
            for (int half = 0; half < 2; ++half) {
                int t0 = (b << 6) + half * 32;
                if (t0 > s_max) break;
                if (anysel || (t0 + 31 >= winlo0)) tli[8 + c++] = t0;
            }
        }
        tli[72] = c;
    }
    __syncthreads();
    int nt = tli[72];

    float lS[TQ], lW[TQ];
    float2 aS[TQ][2], aW[TQ][2];
#pragma unroll
    for (int r = 0; r < TQ; ++r) {
        lS[r] = 0.f; lW[r] = 0.f;
        aS[r][0] = {0.f, 0.f}; aS[r][1] = {0.f, 0.f};
        aW[r][0] = {0.f, 0.f}; aW[r][1] = {0.f, 0.f};
    }

    // ---- main prologue: prefetch K(0) ----
    if (nt > 0) {
        int t0 = tli[8];
#pragma unroll
        for (int rr = 0; rr < 4; ++rr) {
            int row = st_row + 8 * rr;
            cp_async16(kb0 + row * KP + 4 * st_d4,
                       kg + ((size_t)(t0 + row) * HK + n) * D + 4 * st_d4);
        }
    }
    CP_COMMIT();   // group: K(0)

    for (int i = 0; i < nt; ++i) {
        int t0 = tli[8 + i];
        float* kcur = (i & 1) ? kb1 : kb0;
        float* knxt = (i & 1) ? kb0 : kb1;
        bool hasnxt = (i + 1 < nt);

        __syncthreads();   // S1: vsm free (PV(i-1) done), knxt free

        // V(i) -> vsm  (own group)
#pragma unroll
        for (int rr = 0; rr < 4; ++rr) {
            int row = st_row + 8 * rr;
            cp_async16(vsm + row * KP + 4 * st_d4,
                       vg + ((size_t)(t0 + row) * HK + n) * D + 4 * st_d4);
        }
        CP_COMMIT();   // group: V(i)

        if (hasnxt) {
            int t0n = tli[8 + i + 1];
#pragma unroll
            for (int rr = 0; rr < 4; ++rr) {
                int row = st_row + 8 * rr;
                cp_async16(knxt + row * KP + 4 * st_d4,
                           kg + ((size_t)(t0n + row) * HK + n) * D + 4 * st_d4);
            }
            CP_COMMIT();   // group: K(i+1)
        }

        if (hasnxt) { CP_WAIT(2); } else { CP_WAIT(1); }   // K(i) complete
        __syncthreads();   // S2: K(i) visible

        // per-row flags (warp-uniform; identical across warps)
        int b = t0 >> 6;
        int selb = 0, winb = 0;
#pragma unroll
        for (int r = 0; r < TQ; ++r) {
            int s_r = s0 + r;
            int wl = s_r - WIN; if (wl < 0) wl = 0;
            bool ok = (t0 <= s_r);
            if (ok && (((unsigned)tli[r] >> b) & 1u)) selb |= 1 << r;
            if (ok && (t0 + 31 >= wl)) winb |= 1 << r;
        }
        int actb = selb | winb;
        int j = t0 + lane;

        // ---- scores (predicated on per-row activity) ----
        float2 a2[TQ];
#pragma unroll
        for (int r = 0; r < TQ; ++r) a2[r] = make_float2(0.f, 0.f);
#pragma unroll 8
        for (int d4 = 0; d4 < 32; ++d4) {
            float4 kk = *reinterpret_cast<const float4*>(kcur + lane * KP + 4 * d4);
#pragma unroll
            for (int r = 0; r < TQ; ++r) {
                if ((actb >> r) & 1) {
                    float4 qq = *reinterpret_cast<const float4*>(qsm + (r * 8 + h) * 128 + 4 * d4);
                    a2[r] = ffma2({qq.x, qq.y}, {kk.x, kk.y}, a2[r]);
                    a2[r] = ffma2({qq.z, qq.w}, {kk.z, kk.w}, a2[r]);
                }
            }
        }

        // ---- max-free softmax; p -> psm (pitch 20, guarded writes) ----
#pragma unroll
        for (int r = 0; r < TQ; ++r) {
            if (!((actb >> r) & 1)) continue;
            int s_r = s0 + r;
            int wl = s_r - WIN; if (wl < 0) wl = 0;
            bool ins = (selb >> r) & 1;
            bool contrib = (j <= s_r) && (ins || (j >= wl));
            float pe = contrib ? ex2a((a2[r].x + a2[r].y) * SCL2E) : 0.f;
            float pS = ins ? pe : 0.f;
            float pW = (j >= wl) ? pe : 0.f;
            lS[r] += pS;
            lW[r] += pW;
            *reinterpret_cast<float2*>(psm + (h * 32 + lane) * PSP + 2 * r) =
                make_float2(pS, pW);
        }

        if (hasnxt) { CP_WAIT(1); } else { CP_WAIT(0); }   // V(i) complete
        __syncthreads();   // S3: V(i) visible (also orders psm writes->reads)

        // ---- PV: lane = d-quad; p via single aligned LDS.128 broadcast ----
#pragma unroll 4
        for (int tt = 0; tt < 32; ++tt) {
            float4 vv = *reinterpret_cast<const float4*>(vsm + tt * KP + 4 * lane);
            float2 va = {vv.x, vv.y}, vb = {vv.z, vv.w};
            const float* pb = psm + (h * 32 + tt) * PSP;
#pragma unroll
            for (int rp = 0; rp < 4; ++rp) {
                float4 pq = *reinterpret_cast<const float4*>(pb + 4 * rp);
                int r0 = 2 * rp, r1 = r0 + 1;
                if ((selb >> r0) & 1) {
                    aS[r0][0] = ffma2({pq.x, pq.x}, va, aS[r0][0]);
                    aS[r0][1] = ffma2({pq.x, pq.x}, vb, aS[r0][1]);
                }
                if ((winb >> r0) & 1) {
                    aW[r0][0] = ffma2({pq.y, pq.y}, va, aW[r0][0]);
                    aW[r0][1] = ffma2({pq.y, pq.y}, vb, aW[r0][1]);
                }
                if ((selb >> r1) & 1) {
                    aS[r1][0] = ffma2({pq.z, pq.z}, va, aS[r1][0]);
                    aS[r1][1] = ffma2({pq.z, pq.z}, vb, aS[r1][1]);
                }
                if ((winb >> r1) & 1) {
                    aW[r1][0] = ffma2({pq.w, pq.w}, va, aW[r1][0]);
                    aW[r1][1] = ffma2({pq.w, pq.w}, vb, aW[r1][1]);
                }
            }
        }
    }

    // ---- finalize: gates + combine (wg hoisted, ex2 sigmoid) ----
    float wgr[12];
#pragma unroll
    for (int i2 = 0; i2 < 12; ++i2) wgr[i2] = wg[(4 * lane) * 3 + i2];
    float bgr0 = bg[0], bgr1 = bg[1], bgr2 = bg[2];
#pragma unroll
    for (int r = 0; r < TQ; ++r) {
        int s_r = s0 + r;
        float4 q4 = *reinterpret_cast<const float4*>(qsm + (r * 8 + h) * 128 + 4 * lane);
        float gt[3];
#pragma unroll
        for (int c = 0; c < 3; ++c) {
            float gp = q4.x * wgr[0 + c] + q4.y * wgr[3 + c]
                     + q4.z * wgr[6 + c] + q4.w * wgr[9 + c];
            gp = warp_sum(gp) + (c == 0 ? bgr0 : (c == 1 ? bgr1 : bgr2));
            gt[c] = 1.f / (1.f + ex2a(-gp * L2E));
        }
        float iS = 1.f / warp_sum(lS[r]);
        float iW = 1.f / warp_sum(lW[r]);
        float4 c4 = *reinterpret_cast<const float4*>(&g_cmp_o[s_r][n * GQA + h][4 * lane]);
        float4 o4;
        o4.x = c4.x * gt[0] + aS[r][0].x * iS * gt[1] + aW[r][0].x * iW * gt[2];
        o4.y = c4.y * gt[0] + aS[r][0].y * iS * gt[1] + aW[r][0].y * iW * gt[2];
        o4.z = c4.z * gt[0] + aS[r][1].x * iS * gt[1] + aW[r][1].x * iW * gt[2];
        o4.w = c4.w * gt[0] + aS[r][1].y * iS * gt[1] + aW[r][1].y * iW * gt[2];
        *reinterpret_cast<float4*>(out + ((size_t)s_r * HQ + n * GQA + h) * D + 4 * lane) = o4;
    }
}

// ============================================================
// launch  (inputs: q, k, v, w_cmp_k, w_cmp_v, w_gate, b_gate)
// ============================================================
extern "C" void kernel_launch(void* const* d_in, const int* in_sizes, int n_in,
                              void* d_out, int out_size) {
    const float* q   = (const float*)d_in[0];
    const float* k   = (const float*)d_in[1];
    const float* v   = (const float*)d_in[2];
    const float* wck = (const float*)d_in[3];
    const float* wcv = (const float*)d_in[4];
    const float* wg  = (const float*)d_in[5];
    const float* bg  = (const float*)d_in[6];
    float* out = (float*)d_out;

    const int smemF = (8192 + 2 * 4224 + 4224 + 5120) * 4 + 73 * 4;
    cudaFuncSetAttribute(k_fused, cudaFuncAttributeMaxDynamicSharedMemorySize, smemF);

    k_compress<<<dim3(TBLK, HK), D>>>(k, v, wck, wcv);
    k_fused<<<dim3(S_LEN / TQ, HK), 256, smemF>>>(q, k, v, wg, bg, out);
}